// round 12
// baseline (speedup 1.0000x reference)
#include <cuda_runtime.h>
#include <cuda_bf16.h>
#include <math_constants.h>

typedef unsigned int u32;

// ---------------- problem constants ----------------
constexpr int N_  = 20000;
constexpr int E_  = 200000;
constexpr int H_  = 4;
constexpr int C_  = 64;
constexpr int G_  = 64;
constexpr int NC_ = 751;
constexpr int HC_ = H_ * C_;       // 256

// ---------------- scratch (device globals; no allocation allowed) ----------------
__device__ float    d_xl1[(size_t)N_ * HC_];
__device__ float    d_xr1[(size_t)N_ * HC_];
__device__ float    d_ep1[(size_t)E_ * HC_];
__device__ float    d_ep2[(size_t)E_ * C_];
__device__ float    d_lep1[(size_t)N_ * HC_];
__device__ float    d_lep2[(size_t)N_ * C_];
__device__ float    d_h1[(size_t)N_ * HC_];
__device__ float    d_h2[(size_t)N_ * C_];
__device__ float    d_xl2[(size_t)N_ * C_];
__device__ float    d_xr2[(size_t)N_ * C_];
__device__ unsigned d_gmax[G_ * C_];

// split-bf16 weight buffers: [N rows][K cols] K-major (transposed from input [K][N])
__device__ __nv_bfloat16 d_Bep_hi[320 * 384];
__device__ __nv_bfloat16 d_Bep_lo[320 * 384];
__device__ __nv_bfloat16 d_Bx_hi[512 * 512];
__device__ __nv_bfloat16 d_Bx_lo[512 * 512];
__device__ __nv_bfloat16 d_Bh_hi[128 * 256];
__device__ __nv_bfloat16 d_Bh_lo[128 * 256];

// CSR structures
__device__ int d_cnt_row[N_];
__device__ int d_cnt_col[N_];
__device__ int d_rowptr[N_ + 1];
__device__ int d_colptr[N_ + 1];
__device__ int d_rowcur[N_];
__device__ int d_colcur[N_];
__device__ int d_rowe[E_];
__device__ int d_rowj[E_];
__device__ int d_cole[E_];

// ---------------- helpers ----------------
__device__ __forceinline__ unsigned fenc(float f) {
    unsigned u = __float_as_uint(f);
    return (u & 0x80000000u) ? ~u : (u | 0x80000000u);
}
__device__ __forceinline__ float fdec(unsigned u) {
    u = (u & 0x80000000u) ? (u & 0x7fffffffu) : ~u;
    return __uint_as_float(u);
}
constexpr unsigned ENC_NEG_INF = 0x007fffffu;

__device__ __forceinline__ u32 pack_bf16(float x, float y) {
    unsigned short lo = __bfloat16_as_ushort(__float2bfloat16(x));
    unsigned short hi = __bfloat16_as_ushort(__float2bfloat16(y));
    return (u32)lo | ((u32)hi << 16);
}
__device__ __forceinline__ float bf_res(float x) {
    return x - __bfloat162float(__float2bfloat16(x));
}

__device__ __forceinline__ void mma16816(float& c0, float& c1, float& c2, float& c3,
                                         u32 a0, u32 a1, u32 a2, u32 a3,
                                         u32 b0, u32 b1) {
    asm volatile(
        "mma.sync.aligned.m16n8k16.row.col.f32.bf16.bf16.f32 "
        "{%0,%1,%2,%3}, {%4,%5,%6,%7}, {%8,%9}, {%0,%1,%2,%3};"
        : "+f"(c0), "+f"(c1), "+f"(c2), "+f"(c3)
        : "r"(a0), "r"(a1), "r"(a2), "r"(a3), "r"(b0), "r"(b1));
}

// ---------------- weight prep: transpose + bf16 split ----------------
__global__ void prep_weights(const float* __restrict__ W1e, const float* __restrict__ W2e,
                             const float* __restrict__ W1l, const float* __restrict__ W1r,
                             const float* __restrict__ W2l, const float* __restrict__ W2r) {
    int idx = blockIdx.x * blockDim.x + threadIdx.x;
    if (idx < 320 * 384) {
        int n = idx / 384;
        int k = idx % 384;
        float v = (n < 256) ? W1e[k * 256 + n] : W2e[k * 64 + (n - 256)];
        __nv_bfloat16 h = __float2bfloat16(v);
        d_Bep_hi[idx] = h;
        d_Bep_lo[idx] = __float2bfloat16(v - __bfloat162float(h));
    }
    if (idx < 512 * 512) {
        int n = idx >> 9;
        int k = idx & 511;
        float v = (n < 256) ? W1l[k * 256 + n] : W1r[k * 256 + (n - 256)];
        __nv_bfloat16 h = __float2bfloat16(v);
        d_Bx_hi[idx] = h;
        d_Bx_lo[idx] = __float2bfloat16(v - __bfloat162float(h));
    }
    if (idx < 128 * 256) {
        int n = idx >> 8;
        int k = idx & 255;
        float v = (n < 64) ? W2l[k * 64 + n] : W2r[k * 64 + (n - 64)];
        __nv_bfloat16 h = __float2bfloat16(v);
        d_Bh_hi[idx] = h;
        d_Bh_lo[idx] = __float2bfloat16(v - __bfloat162float(h));
    }
}

// ---------------- mma.sync split-bf16 GEMM (R10 layout; sub-step grouped 3-term) ----------------
// smem rows (400B stride): A = [hi(128B)|lo(128B)|hi(128B)], B = [hi|hi|lo].
// Per 16-col sub-step: load a_hi,b_hi -> mma; load a_lo -> mma (b_hi reused);
// load b_lo -> mma (a_hi reused). Same 48 mma/chunk, 33% fewer LDS than the
// sequential 192-col sweep.
__global__ __launch_bounds__(256) void mma_gemm(
    const float* __restrict__ A, int K, int M,
    const __nv_bfloat16* __restrict__ Bhi, const __nv_bfloat16* __restrict__ Blo,
    float* __restrict__ out1, float* __restrict__ out2,
    const float* __restrict__ bias1, const float* __restrict__ bias2,
    int N1, int N2)
{
    extern __shared__ char smem[];
    char* Asm = smem;            // 128 rows * 400B = 51200
    char* Bsm = smem + 51200;    // 51200

    const int tid = threadIdx.x;
    const int wid = tid >> 5;
    const int lane = tid & 31;
    const int m0 = blockIdx.y * 128;   // row-block: slow dimension
    const int n0 = blockIdx.x * 128;   // col-block: fast dimension (L2 reuse of A)
    const int NT = N1 + N2;
    const int warpRow = (wid & 3) * 32;
    const int warpCol = (wid >> 2) * 64;

    float acc[2][8][4];
    #pragma unroll
    for (int i = 0; i < 2; i++)
        #pragma unroll
        for (int j = 0; j < 8; j++)
            #pragma unroll
            for (int q = 0; q < 4; q++)
                acc[i][j][q] = 0.f;

    for (int k0 = 0; k0 < K; k0 += 64) {
        __syncthreads();
        // ---- A chunk: 128 rows x 64 fp32 -> bf16 hi/lo concat ----
        #pragma unroll
        for (int it = 0; it < 8; it++) {
            int idx = tid + it * 256;
            int r = idx >> 4;
            int q = idx & 15;
            float4 v = make_float4(0.f, 0.f, 0.f, 0.f);
            if (m0 + r < M) v = *(const float4*)(A + (size_t)(m0 + r) * K + k0 + q * 4);
            u32 h0 = pack_bf16(v.x, v.y);
            u32 h1 = pack_bf16(v.z, v.w);
            u32 l0 = pack_bf16(bf_res(v.x), bf_res(v.y));
            u32 l1 = pack_bf16(bf_res(v.z), bf_res(v.w));
            char* rowp = Asm + r * 400 + q * 8;
            *(uint2*)(rowp)       = make_uint2(h0, h1);
            *(uint2*)(rowp + 128) = make_uint2(l0, l1);
            *(uint2*)(rowp + 256) = make_uint2(h0, h1);
        }
        // ---- B chunk: 128 rows x 64 bf16 hi/lo concat [hi|hi|lo] ----
        #pragma unroll
        for (int it = 0; it < 4; it++) {
            int idx = tid + it * 256;
            int n = idx >> 3;
            int q = idx & 7;
            uint4 vh = make_uint4(0u, 0u, 0u, 0u);
            uint4 vl = vh;
            if (n0 + n < NT) {
                vh = *(const uint4*)(Bhi + (size_t)(n0 + n) * K + k0 + q * 8);
                vl = *(const uint4*)(Blo + (size_t)(n0 + n) * K + k0 + q * 8);
            }
            char* rowp = Bsm + n * 400 + q * 16;
            *(uint4*)(rowp)       = vh;
            *(uint4*)(rowp + 128) = vh;
            *(uint4*)(rowp + 256) = vl;
        }
        __syncthreads();

        // ---- 4 sub-steps x 3 terms, fragments reused across terms ----
        #pragma unroll
        for (int sub = 0; sub < 4; sub++) {
            const int kh = sub * 16;        // hi columns (A and B)
            const int kl = 64 + sub * 16;   // A-lo columns
            const int kb = 128 + sub * 16;  // B-lo columns

            u32 ah[2][4];
            #pragma unroll
            for (int mt = 0; mt < 2; mt++) {
                const char* ap = Asm + (warpRow + mt * 16 + (lane >> 2)) * 400
                               + (kh + (lane & 3) * 2) * 2;
                ah[mt][0] = *(const u32*)(ap);
                ah[mt][1] = *(const u32*)(ap + 8 * 400);
                ah[mt][2] = *(const u32*)(ap + 16);
                ah[mt][3] = *(const u32*)(ap + 8 * 400 + 16);
            }
            u32 bh[8][2];
            #pragma unroll
            for (int nt = 0; nt < 8; nt++) {
                const char* bp = Bsm + (warpCol + nt * 8 + (lane >> 2)) * 400
                               + (kh + (lane & 3) * 2) * 2;
                bh[nt][0] = *(const u32*)(bp);
                bh[nt][1] = *(const u32*)(bp + 16);
            }
            #pragma unroll
            for (int mt = 0; mt < 2; mt++)
                #pragma unroll
                for (int nt = 0; nt < 8; nt++)
                    mma16816(acc[mt][nt][0], acc[mt][nt][1], acc[mt][nt][2], acc[mt][nt][3],
                             ah[mt][0], ah[mt][1], ah[mt][2], ah[mt][3], bh[nt][0], bh[nt][1]);

            u32 al[2][4];
            #pragma unroll
            for (int mt = 0; mt < 2; mt++) {
                const char* ap = Asm + (warpRow + mt * 16 + (lane >> 2)) * 400
                               + (kl + (lane & 3) * 2) * 2;
                al[mt][0] = *(const u32*)(ap);
                al[mt][1] = *(const u32*)(ap + 8 * 400);
                al[mt][2] = *(const u32*)(ap + 16);
                al[mt][3] = *(const u32*)(ap + 8 * 400 + 16);
            }
            #pragma unroll
            for (int mt = 0; mt < 2; mt++)
                #pragma unroll
                for (int nt = 0; nt < 8; nt++)
                    mma16816(acc[mt][nt][0], acc[mt][nt][1], acc[mt][nt][2], acc[mt][nt][3],
                             al[mt][0], al[mt][1], al[mt][2], al[mt][3], bh[nt][0], bh[nt][1]);

            u32 bl[8][2];
            #pragma unroll
            for (int nt = 0; nt < 8; nt++) {
                const char* bp = Bsm + (warpCol + nt * 8 + (lane >> 2)) * 400
                               + (kb + (lane & 3) * 2) * 2;
                bl[nt][0] = *(const u32*)(bp);
                bl[nt][1] = *(const u32*)(bp + 16);
            }
            #pragma unroll
            for (int mt = 0; mt < 2; mt++)
                #pragma unroll
                for (int nt = 0; nt < 8; nt++)
                    mma16816(acc[mt][nt][0], acc[mt][nt][1], acc[mt][nt][2], acc[mt][nt][3],
                             ah[mt][0], ah[mt][1], ah[mt][2], ah[mt][3], bl[nt][0], bl[nt][1]);
        }
    }

    // ---- epilogue ----
    #pragma unroll
    for (int mt = 0; mt < 2; mt++) {
        int r0 = m0 + warpRow + mt * 16 + (lane >> 2);
        #pragma unroll
        for (int nt = 0; nt < 8; nt++) {
            int gc = n0 + warpCol + nt * 8 + (lane & 3) * 2;
            if (gc >= NT) continue;
            float* o;
            const float* bs;
            int Nn, cc;
            if (gc < N1) { o = out1; bs = bias1; Nn = N1; cc = gc; }
            else         { o = out2; bs = bias2; Nn = N2; cc = gc - N1; }
            float bv0 = 0.f, bv1 = 0.f;
            if (bs != 0) { bv0 = bs[cc]; bv1 = bs[cc + 1]; }
            if (r0 < M) {
                float2 w = make_float2(acc[mt][nt][0] + bv0, acc[mt][nt][1] + bv1);
                *(float2*)(o + (size_t)r0 * Nn + cc) = w;
            }
            if (r0 + 8 < M) {
                float2 w = make_float2(acc[mt][nt][2] + bv0, acc[mt][nt][3] + bv1);
                *(float2*)(o + (size_t)(r0 + 8) * Nn + cc) = w;
            }
        }
    }
}

// ---------------- init ----------------
__global__ void init_kernel() {
    int i0 = blockIdx.x * blockDim.x + threadIdx.x;
    int stride = gridDim.x * blockDim.x;
    for (int i = i0; i < N_; i += stride) {
        d_cnt_row[i] = 0;
        d_cnt_col[i] = 0;
    }
    for (int i = i0; i < G_ * C_; i += stride) d_gmax[i] = ENC_NEG_INF;
}

__global__ void cnt_kernel(const int* __restrict__ row, const int* __restrict__ col) {
    int e = blockIdx.x * blockDim.x + threadIdx.x;
    if (e < E_) {
        atomicAdd(&d_cnt_row[row[e]], 1);
        atomicAdd(&d_cnt_col[col[e]], 1);
    }
}

__global__ __launch_bounds__(256) void scan_kernel() {
    __shared__ int warpsums[8];
    __shared__ int s_carry;
    int tid = threadIdx.x;
    const int* cnt = (blockIdx.x == 0) ? d_cnt_row : d_cnt_col;
    int* ptr       = (blockIdx.x == 0) ? d_rowptr  : d_colptr;
    if (tid == 0) s_carry = 0;
    __syncthreads();
    for (int base = 0; base < N_; base += 256) {
        int v = (base + tid < N_) ? cnt[base + tid] : 0;
        int x = v;
        #pragma unroll
        for (int o = 1; o < 32; o <<= 1) {
            int y = __shfl_up_sync(0xffffffffu, x, o);
            if ((tid & 31) >= o) x += y;
        }
        if ((tid & 31) == 31) warpsums[tid >> 5] = x;
        __syncthreads();
        if (tid < 8) {
            int w = warpsums[tid];
            #pragma unroll
            for (int o = 1; o < 8; o <<= 1) {
                int y = __shfl_up_sync(0xffu, w, o);
                if (tid >= o) w += y;
            }
            warpsums[tid] = w;
        }
        __syncthreads();
        int prev = (tid >= 32) ? warpsums[(tid >> 5) - 1] : 0;
        if (base + tid < N_) ptr[base + tid] = s_carry + prev + x - v;
        __syncthreads();
        if (tid == 0) s_carry += warpsums[7];
        __syncthreads();
    }
    if (tid == 0) ptr[N_] = s_carry;
}

__global__ void copycur_kernel() {
    int i = blockIdx.x * blockDim.x + threadIdx.x;
    if (i < N_) {
        d_rowcur[i] = d_rowptr[i];
        d_colcur[i] = d_colptr[i];
    }
}

__global__ void fill_kernel(const int* __restrict__ row, const int* __restrict__ col) {
    int e = blockIdx.x * blockDim.x + threadIdx.x;
    if (e >= E_) return;
    int j = col[e];
    int p = atomicAdd(&d_rowcur[row[e]], 1);
    d_rowe[p] = e;
    d_rowj[p] = j;
    int q = atomicAdd(&d_colcur[j], 1);
    d_cole[q] = e;
}

// ---------------- self-loop attr projection: CSR gather mean ----------------
__global__ __launch_bounds__(320) void lep_kernel() {
    int n = blockIdx.x;
    int tid = threadIdx.x;
    int beg = d_colptr[n];
    int end = d_colptr[n + 1];
    float s = 0.f;
    if (tid < HC_) {
        for (int idx = beg; idx < end; idx++)
            s += d_ep1[(size_t)d_cole[idx] * HC_ + tid];
    } else {
        int c = tid - HC_;
        for (int idx = beg; idx < end; idx++)
            s += d_ep2[(size_t)d_cole[idx] * C_ + c];
    }
    float inv = 1.0f / (float)max(end - beg, 1);
    if (tid < HC_) d_lep1[(size_t)n * HC_ + tid] = s * inv;
    else           d_lep2[(size_t)n * C_ + (tid - HC_)] = s * inv;
}

// ---------------- layer 1 attention: block per node, online softmax ----------------
__global__ __launch_bounds__(256) void att1_kernel(const float* __restrict__ att,
                                                   const float* __restrict__ bias) {
    int i = blockIdx.x;
    int tid = threadIdx.x;
    int h = tid >> 6;
    int lane = tid & 31;
    int wid = tid >> 5;
    __shared__ float s_red[2][8];

    float xr_c = d_xr1[(size_t)i * HC_ + tid];
    float att_c = att[tid];

    int beg = d_rowptr[i];
    int end = d_rowptr[i + 1];

    float m = -CUDART_INF_F;
    float den = 0.f;
    float acc = 0.f;

    float xlv, epv;
    if (beg < end) {
        int e = d_rowe[beg];
        int j = d_rowj[beg];
        xlv = d_xl1[(size_t)j * HC_ + tid];
        epv = d_ep1[(size_t)e * HC_ + tid];
    } else {
        xlv = d_xl1[(size_t)i * HC_ + tid];
        epv = d_lep1[(size_t)i * HC_ + tid];
    }

    for (int idx = beg; idx <= end; idx++) {
        float xl_c = xlv;
        float ep_c = epv;
        int nxt = idx + 1;
        if (nxt < end) {
            int e = d_rowe[nxt];
            int j = d_rowj[nxt];
            xlv = d_xl1[(size_t)j * HC_ + tid];
            epv = d_ep1[(size_t)e * HC_ + tid];
        } else if (nxt == end) {
            xlv = d_xl1[(size_t)i * HC_ + tid];
            epv = d_lep1[(size_t)i * HC_ + tid];
        }

        float v = xl_c + xr_c + ep_c;
        v = v > 0.f ? v : 0.2f * v;
        float t = v * att_c;
        #pragma unroll
        for (int o = 1; o < 32; o <<= 1) t += __shfl_xor_sync(0xffffffffu, t, o);
        int buf = idx & 1;
        if (lane == 0) s_red[buf][wid] = t;
        __syncthreads();
        float logit = s_red[buf][2 * h] + s_red[buf][2 * h + 1];

        float mn = fmaxf(m, logit);
        float sc = __expf(m - mn);
        float ex = __expf(logit - mn);
        den = den * sc + ex;
        acc = acc * sc + xl_c * ex;
        m = mn;
    }

    float outv = acc / den + bias[tid];
    d_h1[(size_t)i * HC_ + tid] = outv > 0.f ? outv : 0.01f * outv;
}

// ---------------- layer 2 attention: warp per node ----------------
__global__ __launch_bounds__(256) void att2_kernel(const float* __restrict__ att,
                                                   const float* __restrict__ bias) {
    int i = (blockIdx.x * blockDim.x + threadIdx.x) >> 5;
    int lane = threadIdx.x & 31;
    if (i >= N_) return;

    float2 xr = ((const float2*)(d_xr2 + (size_t)i * C_))[lane];
    float2 at = ((const float2*)att)[lane];

    int beg = d_rowptr[i];
    int end = d_rowptr[i + 1];
    float m = -CUDART_INF_F;
    float den = 0.f;
    float accx = 0.f;
    float accy = 0.f;

    float2 xlv, epv;
    if (beg < end) {
        int e = d_rowe[beg];
        int j = d_rowj[beg];
        xlv = ((const float2*)(d_xl2 + (size_t)j * C_))[lane];
        epv = ((const float2*)(d_ep2 + (size_t)e * C_))[lane];
    } else {
        xlv = ((const float2*)(d_xl2 + (size_t)i * C_))[lane];
        epv = ((const float2*)(d_lep2 + (size_t)i * C_))[lane];
    }

    for (int idx = beg; idx <= end; idx++) {
        float2 xl = xlv;
        float2 e2 = epv;
        int nxt = idx + 1;
        if (nxt < end) {
            int e = d_rowe[nxt];
            int j = d_rowj[nxt];
            xlv = ((const float2*)(d_xl2 + (size_t)j * C_))[lane];
            epv = ((const float2*)(d_ep2 + (size_t)e * C_))[lane];
        } else if (nxt == end) {
            xlv = ((const float2*)(d_xl2 + (size_t)i * C_))[lane];
            epv = ((const float2*)(d_lep2 + (size_t)i * C_))[lane];
        }

        float v0 = xl.x + xr.x + e2.x;
        v0 = v0 > 0.f ? v0 : 0.2f * v0;
        float v1 = xl.y + xr.y + e2.y;
        v1 = v1 > 0.f ? v1 : 0.2f * v1;
        float t = v0 * at.x + v1 * at.y;
        #pragma unroll
        for (int o = 1; o < 32; o <<= 1) t += __shfl_xor_sync(0xffffffffu, t, o);

        float mn = fmaxf(m, t);
        float sc = __expf(m - mn);
        float ex = __expf(t - mn);
        den = den * sc + ex;
        accx = accx * sc + xl.x * ex;
        accy = accy * sc + xl.y * ex;
        m = mn;
    }

    float2 bv = ((const float2*)bias)[lane];
    float o0 = accx / den + bv.x;
    float o1 = accy / den + bv.y;
    o0 = o0 > 0.f ? o0 : 0.01f * o0;
    o1 = o1 > 0.f ? o1 : 0.01f * o1;
    ((float2*)(d_h2 + (size_t)i * C_))[lane] = make_float2(o0, o1);
}

// ---------------- global max pool ----------------
__global__ void pool_kernel(const int* __restrict__ batch) {
    int idx = blockIdx.x * blockDim.x + threadIdx.x;
    if (idx >= N_ * C_) return;
    int n = idx >> 6;
    int c = idx & 63;
    atomicMax(&d_gmax[batch[n] * C_ + c], fenc(d_h2[idx]));
}

// ---------------- layernorm + classifier ----------------
__global__ void final_kernel(const float* __restrict__ ln_g, const float* __restrict__ ln_b,
                             const float* __restrict__ clf_W, const float* __restrict__ clf_b,
                             float* __restrict__ out, int out_size) {
    int g = blockIdx.x;
    int tid = threadIdx.x;
    __shared__ float sg[C_];
    __shared__ float sgn[C_];
    __shared__ float s_mu, s_rstd;
    if (tid < C_) sg[tid] = fdec(d_gmax[g * C_ + tid]);
    __syncthreads();
    if (tid == 0) {
        float m = 0.f;
        for (int c = 0; c < C_; c++) m += sg[c];
        m *= (1.0f / C_);
        float v = 0.f;
        for (int c = 0; c < C_; c++) {
            float dd = sg[c] - m;
            v += dd * dd;
        }
        v *= (1.0f / C_);
        s_mu = m;
        s_rstd = rsqrtf(v + 1e-5f);
    }
    __syncthreads();
    if (tid < C_) {
        float gn = (sg[tid] - s_mu) * s_rstd * ln_g[tid] + ln_b[tid];
        sgn[tid] = gn;
        if (out_size >= G_ * NC_ + G_ * C_) out[G_ * NC_ + g * C_ + tid] = gn;
    }
    __syncthreads();
    for (int o = tid; o < NC_; o += blockDim.x) {
        float s = clf_b[o];
        #pragma unroll 8
        for (int c = 0; c < C_; c++) s += sgn[c] * clf_W[c * NC_ + o];
        out[g * NC_ + o] = s;
    }
}

// ---------------- launch ----------------
extern "C" void kernel_launch(void* const* d_in, const int* in_sizes, int n_in,
                              void* d_out, int out_size) {
    const float* x     = (const float*)d_in[0];
    const int*   ei    = (const int*)  d_in[1];
    const float* ea    = (const float*)d_in[2];
    const int*   batch = (const int*)  d_in[3];
    const float* W1l = (const float*)d_in[4];
    const float* b1l  = (const float*)d_in[5];
    const float* W1r = (const float*)d_in[6];
    const float* b1r  = (const float*)d_in[7];
    const float* W1e = (const float*)d_in[8];
    const float* att1 = (const float*)d_in[9];
    const float* bias1 = (const float*)d_in[10];
    const float* W2l = (const float*)d_in[11];
    const float* b2l  = (const float*)d_in[12];
    const float* W2r = (const float*)d_in[13];
    const float* b2r  = (const float*)d_in[14];
    const float* W2e = (const float*)d_in[15];
    const float* att2 = (const float*)d_in[16];
    const float* bias2 = (const float*)d_in[17];
    const float* ln_g = (const float*)d_in[18];
    const float* ln_b = (const float*)d_in[19];
    const float* clfW = (const float*)d_in[20];
    const float* clfb = (const float*)d_in[21];

    const int* row = ei;
    const int* col = ei + E_;
    float* out = (float*)d_out;

    float *p_xl1, *p_xr1, *p_ep1, *p_ep2, *p_h1, *p_xl2, *p_xr2;
    cudaGetSymbolAddress((void**)&p_xl1, d_xl1);
    cudaGetSymbolAddress((void**)&p_xr1, d_xr1);
    cudaGetSymbolAddress((void**)&p_ep1, d_ep1);
    cudaGetSymbolAddress((void**)&p_ep2, d_ep2);
    cudaGetSymbolAddress((void**)&p_h1,  d_h1);
    cudaGetSymbolAddress((void**)&p_xl2, d_xl2);
    cudaGetSymbolAddress((void**)&p_xr2, d_xr2);
    __nv_bfloat16 *pBep_hi, *pBep_lo, *pBx_hi, *pBx_lo, *pBh_hi, *pBh_lo;
    cudaGetSymbolAddress((void**)&pBep_hi, d_Bep_hi);
    cudaGetSymbolAddress((void**)&pBep_lo, d_Bep_lo);
    cudaGetSymbolAddress((void**)&pBx_hi,  d_Bx_hi);
    cudaGetSymbolAddress((void**)&pBx_lo,  d_Bx_lo);
    cudaGetSymbolAddress((void**)&pBh_hi,  d_Bh_hi);
    cudaGetSymbolAddress((void**)&pBh_lo,  d_Bh_lo);

    const int SMEM_MMA = 102400;
    cudaFuncSetAttribute(mma_gemm, cudaFuncAttributeMaxDynamicSharedMemorySize, SMEM_MMA);

    // Launch order places the ep mma_gemm at index 3 (the slot ncu captures).
    prep_weights<<<(512 * 512 + 255) / 256, 256>>>(W1e, W2e, W1l, W1r, W2l, W2r);   // 0
    init_kernel<<<256, 256>>>();                                                     // 1
    cnt_kernel<<<(E_ + 255) / 256, 256>>>(row, col);                                 // 2
    // ep GEMM: grid (NY=3 fast, MX=1563 slow) for A L2 reuse                        // 3
    mma_gemm<<<dim3(3, (E_ + 127) / 128), 256, SMEM_MMA>>>(
        ea, 384, E_, pBep_hi, pBep_lo, p_ep1, p_ep2, (const float*)0, (const float*)0, 256, 64);
    scan_kernel<<<2, 256>>>();                                                       // 4
    copycur_kernel<<<(N_ + 255) / 256, 256>>>();                                     // 5
    fill_kernel<<<(E_ + 255) / 256, 256>>>(row, col);                                // 6
    mma_gemm<<<dim3(4, (N_ + 127) / 128), 256, SMEM_MMA>>>(                          // 7
        x, 512, N_, pBx_hi, pBx_lo, p_xl1, p_xr1, b1l, b1r, 256, 256);

    // self-loop attrs (gather by col)
    lep_kernel<<<N_, 320>>>();

    // layer 1 attention
    att1_kernel<<<N_, 256>>>(att1, bias1);

    // layer 2 transforms
    mma_gemm<<<dim3(1, (N_ + 127) / 128), 256, SMEM_MMA>>>(
        p_h1, 256, N_, pBh_hi, pBh_lo, p_xl2, p_xr2, b2l, b2r, 64, 64);

    // layer 2 attention
    att2_kernel<<<(N_ * 32 + 255) / 256, 256>>>(att2, bias2);

    pool_kernel<<<(N_ * C_ + 255) / 256, 256>>>(batch);
    final_kernel<<<G_, 256>>>(ln_g, ln_b, clfW, clfb, out, out_size);
}

// round 13
// speedup vs baseline: 1.2440x; 1.2440x over previous
#include <cuda_runtime.h>
#include <cuda_bf16.h>
#include <math_constants.h>

typedef unsigned int u32;

// ---------------- problem constants ----------------
constexpr int N_  = 20000;
constexpr int E_  = 200000;
constexpr int H_  = 4;
constexpr int C_  = 64;
constexpr int G_  = 64;
constexpr int NC_ = 751;
constexpr int HC_ = H_ * C_;       // 256

// ---------------- scratch (device globals; no allocation allowed) ----------------
__device__ float    d_xl1[(size_t)N_ * HC_];
__device__ float    d_xr1[(size_t)N_ * HC_];
__device__ float    d_ep1[(size_t)E_ * HC_];
__device__ float    d_ep2[(size_t)E_ * C_];
__device__ float    d_lep1[(size_t)N_ * HC_];
__device__ float    d_lep2[(size_t)N_ * C_];
__device__ float    d_h1[(size_t)N_ * HC_];
__device__ float    d_h2[(size_t)N_ * C_];
__device__ float    d_xl2[(size_t)N_ * C_];
__device__ float    d_xr2[(size_t)N_ * C_];
__device__ unsigned d_gmax[G_ * C_];

// split-bf16 weight buffers: [N rows][K cols] K-major (transposed from input [K][N])
__device__ __nv_bfloat16 d_Bep_hi[320 * 384];
__device__ __nv_bfloat16 d_Bep_lo[320 * 384];
__device__ __nv_bfloat16 d_Bx_hi[512 * 512];
__device__ __nv_bfloat16 d_Bx_lo[512 * 512];
__device__ __nv_bfloat16 d_Bh_hi[128 * 256];
__device__ __nv_bfloat16 d_Bh_lo[128 * 256];

// CSR structures
__device__ int d_cnt_row[N_];
__device__ int d_cnt_col[N_];
__device__ int d_rowptr[N_ + 1];
__device__ int d_colptr[N_ + 1];
__device__ int d_rowcur[N_];
__device__ int d_colcur[N_];
__device__ int d_rowe[E_];
__device__ int d_rowj[E_];
__device__ int d_cole[E_];

// ---------------- helpers ----------------
__device__ __forceinline__ unsigned fenc(float f) {
    unsigned u = __float_as_uint(f);
    return (u & 0x80000000u) ? ~u : (u | 0x80000000u);
}
__device__ __forceinline__ float fdec(unsigned u) {
    u = (u & 0x80000000u) ? (u & 0x7fffffffu) : ~u;
    return __uint_as_float(u);
}
constexpr unsigned ENC_NEG_INF = 0x007fffffu;

__device__ __forceinline__ u32 pack_bf16(float x, float y) {
    unsigned short lo = __bfloat16_as_ushort(__float2bfloat16(x));
    unsigned short hi = __bfloat16_as_ushort(__float2bfloat16(y));
    return (u32)lo | ((u32)hi << 16);
}
__device__ __forceinline__ float bf_res(float x) {
    return x - __bfloat162float(__float2bfloat16(x));
}

__device__ __forceinline__ void mma16816(float& c0, float& c1, float& c2, float& c3,
                                         u32 a0, u32 a1, u32 a2, u32 a3,
                                         u32 b0, u32 b1) {
    asm volatile(
        "mma.sync.aligned.m16n8k16.row.col.f32.bf16.bf16.f32 "
        "{%0,%1,%2,%3}, {%4,%5,%6,%7}, {%8,%9}, {%0,%1,%2,%3};"
        : "+f"(c0), "+f"(c1), "+f"(c2), "+f"(c3)
        : "r"(a0), "r"(a1), "r"(a2), "r"(a3), "r"(b0), "r"(b1));
}

// ---------------- weight prep: transpose + bf16 split ----------------
__global__ void prep_weights(const float* __restrict__ W1e, const float* __restrict__ W2e,
                             const float* __restrict__ W1l, const float* __restrict__ W1r,
                             const float* __restrict__ W2l, const float* __restrict__ W2r) {
    int idx = blockIdx.x * blockDim.x + threadIdx.x;
    if (idx < 320 * 384) {
        int n = idx / 384;
        int k = idx % 384;
        float v = (n < 256) ? W1e[k * 256 + n] : W2e[k * 64 + (n - 256)];
        __nv_bfloat16 h = __float2bfloat16(v);
        d_Bep_hi[idx] = h;
        d_Bep_lo[idx] = __float2bfloat16(v - __bfloat162float(h));
    }
    if (idx < 512 * 512) {
        int n = idx >> 9;
        int k = idx & 511;
        float v = (n < 256) ? W1l[k * 256 + n] : W1r[k * 256 + (n - 256)];
        __nv_bfloat16 h = __float2bfloat16(v);
        d_Bx_hi[idx] = h;
        d_Bx_lo[idx] = __float2bfloat16(v - __bfloat162float(h));
    }
    if (idx < 128 * 256) {
        int n = idx >> 8;
        int k = idx & 255;
        float v = (n < 64) ? W2l[k * 64 + n] : W2r[k * 64 + (n - 64)];
        __nv_bfloat16 h = __float2bfloat16(v);
        d_Bh_hi[idx] = h;
        d_Bh_lo[idx] = __float2bfloat16(v - __bfloat162float(h));
    }
}

// ---------------- mma.sync split-bf16 GEMM (exact R10 version — DO NOT TOUCH) ----------------
__global__ __launch_bounds__(256) void mma_gemm(
    const float* __restrict__ A, int K, int M,
    const __nv_bfloat16* __restrict__ Bhi, const __nv_bfloat16* __restrict__ Blo,
    float* __restrict__ out1, float* __restrict__ out2,
    const float* __restrict__ bias1, const float* __restrict__ bias2,
    int N1, int N2)
{
    extern __shared__ char smem[];
    char* Asm = smem;            // 128 rows * 400B = 51200
    char* Bsm = smem + 51200;    // 51200

    const int tid = threadIdx.x;
    const int wid = tid >> 5;
    const int lane = tid & 31;
    const int m0 = blockIdx.y * 128;   // row-block: slow dimension
    const int n0 = blockIdx.x * 128;   // col-block: fast dimension (L2 reuse of A)
    const int NT = N1 + N2;
    const int warpRow = (wid & 3) * 32;
    const int warpCol = (wid >> 2) * 64;

    float acc[2][8][4];
    #pragma unroll
    for (int i = 0; i < 2; i++)
        #pragma unroll
        for (int j = 0; j < 8; j++)
            #pragma unroll
            for (int q = 0; q < 4; q++)
                acc[i][j][q] = 0.f;

    for (int k0 = 0; k0 < K; k0 += 64) {
        __syncthreads();
        // ---- A chunk: 128 rows x 64 fp32 -> bf16 hi/lo concat ----
        #pragma unroll
        for (int it = 0; it < 8; it++) {
            int idx = tid + it * 256;
            int r = idx >> 4;
            int q = idx & 15;
            float4 v = make_float4(0.f, 0.f, 0.f, 0.f);
            if (m0 + r < M) v = *(const float4*)(A + (size_t)(m0 + r) * K + k0 + q * 4);
            u32 h0 = pack_bf16(v.x, v.y);
            u32 h1 = pack_bf16(v.z, v.w);
            u32 l0 = pack_bf16(bf_res(v.x), bf_res(v.y));
            u32 l1 = pack_bf16(bf_res(v.z), bf_res(v.w));
            char* rowp = Asm + r * 400 + q * 8;
            *(uint2*)(rowp)       = make_uint2(h0, h1);
            *(uint2*)(rowp + 128) = make_uint2(l0, l1);
            *(uint2*)(rowp + 256) = make_uint2(h0, h1);
        }
        // ---- B chunk: 128 rows x 64 bf16 hi/lo concat [hi|hi|lo] ----
        #pragma unroll
        for (int it = 0; it < 4; it++) {
            int idx = tid + it * 256;
            int n = idx >> 3;
            int q = idx & 7;
            uint4 vh = make_uint4(0u, 0u, 0u, 0u);
            uint4 vl = vh;
            if (n0 + n < NT) {
                vh = *(const uint4*)(Bhi + (size_t)(n0 + n) * K + k0 + q * 8);
                vl = *(const uint4*)(Blo + (size_t)(n0 + n) * K + k0 + q * 8);
            }
            char* rowp = Bsm + n * 400 + q * 16;
            *(uint4*)(rowp)       = vh;
            *(uint4*)(rowp + 128) = vh;
            *(uint4*)(rowp + 256) = vl;
        }
        __syncthreads();

        // ---- mma over 192 concat columns (plain LDS fragments; compiler-scheduled) ----
        #pragma unroll
        for (int kk = 0; kk < 192; kk += 16) {
            u32 a[2][4];
            #pragma unroll
            for (int mt = 0; mt < 2; mt++) {
                const char* ap = Asm + (warpRow + mt * 16 + (lane >> 2)) * 400
                               + (kk + (lane & 3) * 2) * 2;
                a[mt][0] = *(const u32*)(ap);
                a[mt][1] = *(const u32*)(ap + 8 * 400);
                a[mt][2] = *(const u32*)(ap + 16);
                a[mt][3] = *(const u32*)(ap + 8 * 400 + 16);
            }
            u32 b[8][2];
            #pragma unroll
            for (int nt = 0; nt < 8; nt++) {
                const char* bp = Bsm + (warpCol + nt * 8 + (lane >> 2)) * 400
                               + (kk + (lane & 3) * 2) * 2;
                b[nt][0] = *(const u32*)(bp);
                b[nt][1] = *(const u32*)(bp + 16);
            }
            #pragma unroll
            for (int mt = 0; mt < 2; mt++)
                #pragma unroll
                for (int nt = 0; nt < 8; nt++)
                    mma16816(acc[mt][nt][0], acc[mt][nt][1], acc[mt][nt][2], acc[mt][nt][3],
                             a[mt][0], a[mt][1], a[mt][2], a[mt][3], b[nt][0], b[nt][1]);
        }
    }

    // ---- epilogue ----
    #pragma unroll
    for (int mt = 0; mt < 2; mt++) {
        int r0 = m0 + warpRow + mt * 16 + (lane >> 2);
        #pragma unroll
        for (int nt = 0; nt < 8; nt++) {
            int gc = n0 + warpCol + nt * 8 + (lane & 3) * 2;
            if (gc >= NT) continue;
            float* o;
            const float* bs;
            int Nn, cc;
            if (gc < N1) { o = out1; bs = bias1; Nn = N1; cc = gc; }
            else         { o = out2; bs = bias2; Nn = N2; cc = gc - N1; }
            float bv0 = 0.f, bv1 = 0.f;
            if (bs != 0) { bv0 = bs[cc]; bv1 = bs[cc + 1]; }
            if (r0 < M) {
                float2 w = make_float2(acc[mt][nt][0] + bv0, acc[mt][nt][1] + bv1);
                *(float2*)(o + (size_t)r0 * Nn + cc) = w;
            }
            if (r0 + 8 < M) {
                float2 w = make_float2(acc[mt][nt][2] + bv0, acc[mt][nt][3] + bv1);
                *(float2*)(o + (size_t)(r0 + 8) * Nn + cc) = w;
            }
        }
    }
}

// ---------------- init ----------------
__global__ void init_kernel() {
    int i0 = blockIdx.x * blockDim.x + threadIdx.x;
    int stride = gridDim.x * blockDim.x;
    for (int i = i0; i < N_; i += stride) {
        d_cnt_row[i] = 0;
        d_cnt_col[i] = 0;
    }
    for (int i = i0; i < G_ * C_; i += stride) d_gmax[i] = ENC_NEG_INF;
}

__global__ void cnt_kernel(const int* __restrict__ row, const int* __restrict__ col) {
    int e = blockIdx.x * blockDim.x + threadIdx.x;
    if (e < E_) {
        atomicAdd(&d_cnt_row[row[e]], 1);
        atomicAdd(&d_cnt_col[col[e]], 1);
    }
}

__global__ __launch_bounds__(256) void scan_kernel() {
    __shared__ int warpsums[8];
    __shared__ int s_carry;
    int tid = threadIdx.x;
    const int* cnt = (blockIdx.x == 0) ? d_cnt_row : d_cnt_col;
    int* ptr       = (blockIdx.x == 0) ? d_rowptr  : d_colptr;
    if (tid == 0) s_carry = 0;
    __syncthreads();
    for (int base = 0; base < N_; base += 256) {
        int v = (base + tid < N_) ? cnt[base + tid] : 0;
        int x = v;
        #pragma unroll
        for (int o = 1; o < 32; o <<= 1) {
            int y = __shfl_up_sync(0xffffffffu, x, o);
            if ((tid & 31) >= o) x += y;
        }
        if ((tid & 31) == 31) warpsums[tid >> 5] = x;
        __syncthreads();
        if (tid < 8) {
            int w = warpsums[tid];
            #pragma unroll
            for (int o = 1; o < 8; o <<= 1) {
                int y = __shfl_up_sync(0xffu, w, o);
                if (tid >= o) w += y;
            }
            warpsums[tid] = w;
        }
        __syncthreads();
        int prev = (tid >= 32) ? warpsums[(tid >> 5) - 1] : 0;
        if (base + tid < N_) ptr[base + tid] = s_carry + prev + x - v;
        __syncthreads();
        if (tid == 0) s_carry += warpsums[7];
        __syncthreads();
    }
    if (tid == 0) ptr[N_] = s_carry;
}

__global__ void copycur_kernel() {
    int i = blockIdx.x * blockDim.x + threadIdx.x;
    if (i < N_) {
        d_rowcur[i] = d_rowptr[i];
        d_colcur[i] = d_colptr[i];
    }
}

__global__ void fill_kernel(const int* __restrict__ row, const int* __restrict__ col) {
    int e = blockIdx.x * blockDim.x + threadIdx.x;
    if (e >= E_) return;
    int j = col[e];
    int p = atomicAdd(&d_rowcur[row[e]], 1);
    d_rowe[p] = e;
    d_rowj[p] = j;
    int q = atomicAdd(&d_colcur[j], 1);
    d_cole[q] = e;
}

// ---------------- self-loop attr projection: CSR gather mean ----------------
__global__ __launch_bounds__(320) void lep_kernel() {
    int n = blockIdx.x;
    int tid = threadIdx.x;
    int beg = d_colptr[n];
    int end = d_colptr[n + 1];
    float s = 0.f;
    if (tid < HC_) {
        for (int idx = beg; idx < end; idx++)
            s += d_ep1[(size_t)d_cole[idx] * HC_ + tid];
    } else {
        int c = tid - HC_;
        for (int idx = beg; idx < end; idx++)
            s += d_ep2[(size_t)d_cole[idx] * C_ + c];
    }
    float inv = 1.0f / (float)max(end - beg, 1);
    if (tid < HC_) d_lep1[(size_t)n * HC_ + tid] = s * inv;
    else           d_lep2[(size_t)n * C_ + (tid - HC_)] = s * inv;
}

// ---------------- layer 1 attention: warp per (node, head) — no barriers ----------------
__global__ __launch_bounds__(256) void att1_kernel(const float* __restrict__ att,
                                                   const float* __restrict__ bias) {
    int w = (blockIdx.x * blockDim.x + threadIdx.x) >> 5;
    int lane = threadIdx.x & 31;
    int i = w >> 2;
    int h = w & 3;
    if (i >= N_) return;
    const int off = h * 64;     // channel offset of this head's 64-wide slice

    float2 xr = ((const float2*)(d_xr1 + (size_t)i * HC_ + off))[lane];
    float2 at = ((const float2*)(att + off))[lane];

    int beg = d_rowptr[i];
    int end = d_rowptr[i + 1];
    float m = -CUDART_INF_F;
    float den = 0.f;
    float accx = 0.f;
    float accy = 0.f;

    float2 xlv, epv;
    if (beg < end) {
        int e = d_rowe[beg];
        int j = d_rowj[beg];
        xlv = ((const float2*)(d_xl1 + (size_t)j * HC_ + off))[lane];
        epv = ((const float2*)(d_ep1 + (size_t)e * HC_ + off))[lane];
    } else {
        xlv = ((const float2*)(d_xl1 + (size_t)i * HC_ + off))[lane];
        epv = ((const float2*)(d_lep1 + (size_t)i * HC_ + off))[lane];
    }

    for (int idx = beg; idx <= end; idx++) {
        float2 xl = xlv;
        float2 e2 = epv;
        int nxt = idx + 1;
        if (nxt < end) {
            int e = d_rowe[nxt];
            int j = d_rowj[nxt];
            xlv = ((const float2*)(d_xl1 + (size_t)j * HC_ + off))[lane];
            epv = ((const float2*)(d_ep1 + (size_t)e * HC_ + off))[lane];
        } else if (nxt == end) {
            xlv = ((const float2*)(d_xl1 + (size_t)i * HC_ + off))[lane];
            epv = ((const float2*)(d_lep1 + (size_t)i * HC_ + off))[lane];
        }

        float v0 = xl.x + xr.x + e2.x;
        v0 = v0 > 0.f ? v0 : 0.2f * v0;
        float v1 = xl.y + xr.y + e2.y;
        v1 = v1 > 0.f ? v1 : 0.2f * v1;
        float t = v0 * at.x + v1 * at.y;
        #pragma unroll
        for (int o = 1; o < 32; o <<= 1) t += __shfl_xor_sync(0xffffffffu, t, o);

        float mn = fmaxf(m, t);
        float sc = __expf(m - mn);
        float ex = __expf(t - mn);
        den = den * sc + ex;
        accx = accx * sc + xl.x * ex;
        accy = accy * sc + xl.y * ex;
        m = mn;
    }

    float2 bv = ((const float2*)(bias + off))[lane];
    float o0 = accx / den + bv.x;
    float o1 = accy / den + bv.y;
    o0 = o0 > 0.f ? o0 : 0.01f * o0;
    o1 = o1 > 0.f ? o1 : 0.01f * o1;
    ((float2*)(d_h1 + (size_t)i * HC_ + off))[lane] = make_float2(o0, o1);
}

// ---------------- layer 2 attention: warp per node ----------------
__global__ __launch_bounds__(256) void att2_kernel(const float* __restrict__ att,
                                                   const float* __restrict__ bias) {
    int i = (blockIdx.x * blockDim.x + threadIdx.x) >> 5;
    int lane = threadIdx.x & 31;
    if (i >= N_) return;

    float2 xr = ((const float2*)(d_xr2 + (size_t)i * C_))[lane];
    float2 at = ((const float2*)att)[lane];

    int beg = d_rowptr[i];
    int end = d_rowptr[i + 1];
    float m = -CUDART_INF_F;
    float den = 0.f;
    float accx = 0.f;
    float accy = 0.f;

    float2 xlv, epv;
    if (beg < end) {
        int e = d_rowe[beg];
        int j = d_rowj[beg];
        xlv = ((const float2*)(d_xl2 + (size_t)j * C_))[lane];
        epv = ((const float2*)(d_ep2 + (size_t)e * C_))[lane];
    } else {
        xlv = ((const float2*)(d_xl2 + (size_t)i * C_))[lane];
        epv = ((const float2*)(d_lep2 + (size_t)i * C_))[lane];
    }

    for (int idx = beg; idx <= end; idx++) {
        float2 xl = xlv;
        float2 e2 = epv;
        int nxt = idx + 1;
        if (nxt < end) {
            int e = d_rowe[nxt];
            int j = d_rowj[nxt];
            xlv = ((const float2*)(d_xl2 + (size_t)j * C_))[lane];
            epv = ((const float2*)(d_ep2 + (size_t)e * C_))[lane];
        } else if (nxt == end) {
            xlv = ((const float2*)(d_xl2 + (size_t)i * C_))[lane];
            epv = ((const float2*)(d_lep2 + (size_t)i * C_))[lane];
        }

        float v0 = xl.x + xr.x + e2.x;
        v0 = v0 > 0.f ? v0 : 0.2f * v0;
        float v1 = xl.y + xr.y + e2.y;
        v1 = v1 > 0.f ? v1 : 0.2f * v1;
        float t = v0 * at.x + v1 * at.y;
        #pragma unroll
        for (int o = 1; o < 32; o <<= 1) t += __shfl_xor_sync(0xffffffffu, t, o);

        float mn = fmaxf(m, t);
        float sc = __expf(m - mn);
        float ex = __expf(t - mn);
        den = den * sc + ex;
        accx = accx * sc + xl.x * ex;
        accy = accy * sc + xl.y * ex;
        m = mn;
    }

    float2 bv = ((const float2*)bias)[lane];
    float o0 = accx / den + bv.x;
    float o1 = accy / den + bv.y;
    o0 = o0 > 0.f ? o0 : 0.01f * o0;
    o1 = o1 > 0.f ? o1 : 0.01f * o1;
    ((float2*)(d_h2 + (size_t)i * C_))[lane] = make_float2(o0, o1);
}

// ---------------- global max pool ----------------
__global__ void pool_kernel(const int* __restrict__ batch) {
    int idx = blockIdx.x * blockDim.x + threadIdx.x;
    if (idx >= N_ * C_) return;
    int n = idx >> 6;
    int c = idx & 63;
    atomicMax(&d_gmax[batch[n] * C_ + c], fenc(d_h2[idx]));
}

// ---------------- layernorm + classifier ----------------
__global__ void final_kernel(const float* __restrict__ ln_g, const float* __restrict__ ln_b,
                             const float* __restrict__ clf_W, const float* __restrict__ clf_b,
                             float* __restrict__ out, int out_size) {
    int g = blockIdx.x;
    int tid = threadIdx.x;
    __shared__ float sg[C_];
    __shared__ float sgn[C_];
    __shared__ float s_mu, s_rstd;
    if (tid < C_) sg[tid] = fdec(d_gmax[g * C_ + tid]);
    __syncthreads();
    if (tid == 0) {
        float m = 0.f;
        for (int c = 0; c < C_; c++) m += sg[c];
        m *= (1.0f / C_);
        float v = 0.f;
        for (int c = 0; c < C_; c++) {
            float dd = sg[c] - m;
            v += dd * dd;
        }
        v *= (1.0f / C_);
        s_mu = m;
        s_rstd = rsqrtf(v + 1e-5f);
    }
    __syncthreads();
    if (tid < C_) {
        float gn = (sg[tid] - s_mu) * s_rstd * ln_g[tid] + ln_b[tid];
        sgn[tid] = gn;
        if (out_size >= G_ * NC_ + G_ * C_) out[G_ * NC_ + g * C_ + tid] = gn;
    }
    __syncthreads();
    for (int o = tid; o < NC_; o += blockDim.x) {
        float s = clf_b[o];
        #pragma unroll 8
        for (int c = 0; c < C_; c++) s += sgn[c] * clf_W[c * NC_ + o];
        out[g * NC_ + o] = s;
    }
}

// ---------------- launch ----------------
extern "C" void kernel_launch(void* const* d_in, const int* in_sizes, int n_in,
                              void* d_out, int out_size) {
    const float* x     = (const float*)d_in[0];
    const int*   ei    = (const int*)  d_in[1];
    const float* ea    = (const float*)d_in[2];
    const int*   batch = (const int*)  d_in[3];
    const float* W1l = (const float*)d_in[4];
    const float* b1l  = (const float*)d_in[5];
    const float* W1r = (const float*)d_in[6];
    const float* b1r  = (const float*)d_in[7];
    const float* W1e = (const float*)d_in[8];
    const float* att1 = (const float*)d_in[9];
    const float* bias1 = (const float*)d_in[10];
    const float* W2l = (const float*)d_in[11];
    const float* b2l  = (const float*)d_in[12];
    const float* W2r = (const float*)d_in[13];
    const float* b2r  = (const float*)d_in[14];
    const float* W2e = (const float*)d_in[15];
    const float* att2 = (const float*)d_in[16];
    const float* bias2 = (const float*)d_in[17];
    const float* ln_g = (const float*)d_in[18];
    const float* ln_b = (const float*)d_in[19];
    const float* clfW = (const float*)d_in[20];
    const float* clfb = (const float*)d_in[21];

    const int* row = ei;
    const int* col = ei + E_;
    float* out = (float*)d_out;

    float *p_xl1, *p_xr1, *p_ep1, *p_ep2, *p_h1, *p_xl2, *p_xr2;
    cudaGetSymbolAddress((void**)&p_xl1, d_xl1);
    cudaGetSymbolAddress((void**)&p_xr1, d_xr1);
    cudaGetSymbolAddress((void**)&p_ep1, d_ep1);
    cudaGetSymbolAddress((void**)&p_ep2, d_ep2);
    cudaGetSymbolAddress((void**)&p_h1,  d_h1);
    cudaGetSymbolAddress((void**)&p_xl2, d_xl2);
    cudaGetSymbolAddress((void**)&p_xr2, d_xr2);
    __nv_bfloat16 *pBep_hi, *pBep_lo, *pBx_hi, *pBx_lo, *pBh_hi, *pBh_lo;
    cudaGetSymbolAddress((void**)&pBep_hi, d_Bep_hi);
    cudaGetSymbolAddress((void**)&pBep_lo, d_Bep_lo);
    cudaGetSymbolAddress((void**)&pBx_hi,  d_Bx_hi);
    cudaGetSymbolAddress((void**)&pBx_lo,  d_Bx_lo);
    cudaGetSymbolAddress((void**)&pBh_hi,  d_Bh_hi);
    cudaGetSymbolAddress((void**)&pBh_lo,  d_Bh_lo);

    const int SMEM_MMA = 102400;
    cudaFuncSetAttribute(mma_gemm, cudaFuncAttributeMaxDynamicSharedMemorySize, SMEM_MMA);

    // Launch order places the ep mma_gemm at index 3 (the slot ncu captures).
    prep_weights<<<(512 * 512 + 255) / 256, 256>>>(W1e, W2e, W1l, W1r, W2l, W2r);   // 0
    init_kernel<<<256, 256>>>();                                                     // 1
    cnt_kernel<<<(E_ + 255) / 256, 256>>>(row, col);                                 // 2
    // ep GEMM: grid (NY=3 fast, MX=1563 slow) for A L2 reuse                        // 3
    mma_gemm<<<dim3(3, (E_ + 127) / 128), 256, SMEM_MMA>>>(
        ea, 384, E_, pBep_hi, pBep_lo, p_ep1, p_ep2, (const float*)0, (const float*)0, 256, 64);
    scan_kernel<<<2, 256>>>();                                                       // 4
    copycur_kernel<<<(N_ + 255) / 256, 256>>>();                                     // 5
    fill_kernel<<<(E_ + 255) / 256, 256>>>(row, col);                                // 6
    mma_gemm<<<dim3(4, (N_ + 127) / 128), 256, SMEM_MMA>>>(                          // 7
        x, 512, N_, pBx_hi, pBx_lo, p_xl1, p_xr1, b1l, b1r, 256, 256);

    // self-loop attrs (gather by col)
    lep_kernel<<<N_, 320>>>();

    // layer 1 attention (warp per node-head)
    att1_kernel<<<(N_ * H_ * 32 + 255) / 256, 256>>>(att1, bias1);

    // layer 2 transforms
    mma_gemm<<<dim3(1, (N_ + 127) / 128), 256, SMEM_MMA>>>(
        p_h1, 256, N_, pBh_hi, pBh_lo, p_xl2, p_xr2, b2l, b2r, 64, 64);

    // layer 2 attention
    att2_kernel<<<(N_ * 32 + 255) / 256, 256>>>(att2, bias2);

    pool_kernel<<<(N_ * C_ + 255) / 256, 256>>>(batch);
    final_kernel<<<G_, 256>>>(ln_g, ln_b, clfW, clfb, out, out_size);
}

// round 14
// speedup vs baseline: 1.3166x; 1.0584x over previous
#include <cuda_runtime.h>
#include <cuda_bf16.h>
#include <math_constants.h>

typedef unsigned int u32;

// ---------------- problem constants ----------------
constexpr int N_  = 20000;
constexpr int E_  = 200000;
constexpr int H_  = 4;
constexpr int C_  = 64;
constexpr int G_  = 64;
constexpr int NC_ = 751;
constexpr int HC_ = H_ * C_;       // 256

// ---------------- scratch (device globals; no allocation allowed) ----------------
__device__ float    d_xl1[(size_t)N_ * HC_];
__device__ float    d_xr1[(size_t)N_ * HC_];
__device__ float    d_ep1[(size_t)E_ * HC_];
__device__ float    d_ep2[(size_t)E_ * C_];
__device__ float    d_lep1[(size_t)N_ * HC_];
__device__ float    d_lep2[(size_t)N_ * C_];
__device__ float    d_h1[(size_t)N_ * HC_];
__device__ float    d_h2[(size_t)N_ * C_];
__device__ float    d_xl2[(size_t)N_ * C_];
__device__ float    d_xr2[(size_t)N_ * C_];
__device__ unsigned d_gmax[G_ * C_];

// split-bf16 weight buffers: [N rows][K cols] K-major (transposed from input [K][N])
__device__ __nv_bfloat16 d_Bep_hi[320 * 384];
__device__ __nv_bfloat16 d_Bep_lo[320 * 384];
__device__ __nv_bfloat16 d_Bx_hi[512 * 512];
__device__ __nv_bfloat16 d_Bx_lo[512 * 512];
__device__ __nv_bfloat16 d_Bh_hi[128 * 256];
__device__ __nv_bfloat16 d_Bh_lo[128 * 256];

// CSR structures
__device__ int d_cnt_row[N_];
__device__ int d_cnt_col[N_];
__device__ int d_rowptr[N_ + 1];
__device__ int d_colptr[N_ + 1];
__device__ int d_rowcur[N_];
__device__ int d_colcur[N_];
__device__ int d_rowe[E_];
__device__ int d_rowj[E_];
__device__ int d_cole[E_];

// ---------------- helpers ----------------
__device__ __forceinline__ unsigned fenc(float f) {
    unsigned u = __float_as_uint(f);
    return (u & 0x80000000u) ? ~u : (u | 0x80000000u);
}
__device__ __forceinline__ float fdec(unsigned u) {
    u = (u & 0x80000000u) ? (u & 0x7fffffffu) : ~u;
    return __uint_as_float(u);
}
constexpr unsigned ENC_NEG_INF = 0x007fffffu;

__device__ __forceinline__ u32 pack_bf16(float x, float y) {
    unsigned short lo = __bfloat16_as_ushort(__float2bfloat16(x));
    unsigned short hi = __bfloat16_as_ushort(__float2bfloat16(y));
    return (u32)lo | ((u32)hi << 16);
}
__device__ __forceinline__ float bf_res(float x) {
    return x - __bfloat162float(__float2bfloat16(x));
}

__device__ __forceinline__ void mma16816(float& c0, float& c1, float& c2, float& c3,
                                         u32 a0, u32 a1, u32 a2, u32 a3,
                                         u32 b0, u32 b1) {
    asm volatile(
        "mma.sync.aligned.m16n8k16.row.col.f32.bf16.bf16.f32 "
        "{%0,%1,%2,%3}, {%4,%5,%6,%7}, {%8,%9}, {%0,%1,%2,%3};"
        : "+f"(c0), "+f"(c1), "+f"(c2), "+f"(c3)
        : "r"(a0), "r"(a1), "r"(a2), "r"(a3), "r"(b0), "r"(b1));
}

// ---------------- weight prep: transpose + bf16 split ----------------
__global__ void prep_weights(const float* __restrict__ W1e, const float* __restrict__ W2e,
                             const float* __restrict__ W1l, const float* __restrict__ W1r,
                             const float* __restrict__ W2l, const float* __restrict__ W2r) {
    int idx = blockIdx.x * blockDim.x + threadIdx.x;
    if (idx < 320 * 384) {
        int n = idx / 384;
        int k = idx % 384;
        float v = (n < 256) ? W1e[k * 256 + n] : W2e[k * 64 + (n - 256)];
        __nv_bfloat16 h = __float2bfloat16(v);
        d_Bep_hi[idx] = h;
        d_Bep_lo[idx] = __float2bfloat16(v - __bfloat162float(h));
    }
    if (idx < 512 * 512) {
        int n = idx >> 9;
        int k = idx & 511;
        float v = (n < 256) ? W1l[k * 256 + n] : W1r[k * 256 + (n - 256)];
        __nv_bfloat16 h = __float2bfloat16(v);
        d_Bx_hi[idx] = h;
        d_Bx_lo[idx] = __float2bfloat16(v - __bfloat162float(h));
    }
    if (idx < 128 * 256) {
        int n = idx >> 8;
        int k = idx & 255;
        float v = (n < 64) ? W2l[k * 64 + n] : W2r[k * 64 + (n - 64)];
        __nv_bfloat16 h = __float2bfloat16(v);
        d_Bh_hi[idx] = h;
        d_Bh_lo[idx] = __float2bfloat16(v - __bfloat162float(h));
    }
}

// ---------------- mma.sync split-bf16 GEMM (R10 codegen + dead-column warp skip) ----------------
__global__ __launch_bounds__(256) void mma_gemm(
    const float* __restrict__ A, int K, int M,
    const __nv_bfloat16* __restrict__ Bhi, const __nv_bfloat16* __restrict__ Blo,
    float* __restrict__ out1, float* __restrict__ out2,
    const float* __restrict__ bias1, const float* __restrict__ bias2,
    int N1, int N2)
{
    extern __shared__ char smem[];
    char* Asm = smem;            // 128 rows * 400B = 51200
    char* Bsm = smem + 51200;    // 51200

    const int tid = threadIdx.x;
    const int wid = tid >> 5;
    const int lane = tid & 31;
    const int m0 = blockIdx.y * 128;   // row-block: slow dimension
    const int n0 = blockIdx.x * 128;   // col-block: fast dimension (L2 reuse of A)
    const int NT = N1 + N2;
    const int warpRow = (wid & 3) * 32;
    const int warpCol = (wid >> 2) * 64;
    const bool warpActive = (n0 + warpCol) < NT;   // warp-uniform: skip dead columns

    float acc[2][8][4];
    #pragma unroll
    for (int i = 0; i < 2; i++)
        #pragma unroll
        for (int j = 0; j < 8; j++)
            #pragma unroll
            for (int q = 0; q < 4; q++)
                acc[i][j][q] = 0.f;

    for (int k0 = 0; k0 < K; k0 += 64) {
        __syncthreads();
        // ---- A chunk: 128 rows x 64 fp32 -> bf16 hi/lo concat ----
        #pragma unroll
        for (int it = 0; it < 8; it++) {
            int idx = tid + it * 256;
            int r = idx >> 4;
            int q = idx & 15;
            float4 v = make_float4(0.f, 0.f, 0.f, 0.f);
            if (m0 + r < M) v = *(const float4*)(A + (size_t)(m0 + r) * K + k0 + q * 4);
            u32 h0 = pack_bf16(v.x, v.y);
            u32 h1 = pack_bf16(v.z, v.w);
            u32 l0 = pack_bf16(bf_res(v.x), bf_res(v.y));
            u32 l1 = pack_bf16(bf_res(v.z), bf_res(v.w));
            char* rowp = Asm + r * 400 + q * 8;
            *(uint2*)(rowp)       = make_uint2(h0, h1);
            *(uint2*)(rowp + 128) = make_uint2(l0, l1);
            *(uint2*)(rowp + 256) = make_uint2(h0, h1);
        }
        // ---- B chunk: 128 rows x 64 bf16 hi/lo concat [hi|hi|lo] ----
        #pragma unroll
        for (int it = 0; it < 4; it++) {
            int idx = tid + it * 256;
            int n = idx >> 3;
            int q = idx & 7;
            uint4 vh = make_uint4(0u, 0u, 0u, 0u);
            uint4 vl = vh;
            if (n0 + n < NT) {
                vh = *(const uint4*)(Bhi + (size_t)(n0 + n) * K + k0 + q * 8);
                vl = *(const uint4*)(Blo + (size_t)(n0 + n) * K + k0 + q * 8);
            }
            char* rowp = Bsm + n * 400 + q * 16;
            *(uint4*)(rowp)       = vh;
            *(uint4*)(rowp + 128) = vh;
            *(uint4*)(rowp + 256) = vl;
        }
        __syncthreads();

        // ---- mma over 192 concat columns (plain LDS fragments; compiler-scheduled) ----
        if (warpActive) {
            #pragma unroll
            for (int kk = 0; kk < 192; kk += 16) {
                u32 a[2][4];
                #pragma unroll
                for (int mt = 0; mt < 2; mt++) {
                    const char* ap = Asm + (warpRow + mt * 16 + (lane >> 2)) * 400
                                   + (kk + (lane & 3) * 2) * 2;
                    a[mt][0] = *(const u32*)(ap);
                    a[mt][1] = *(const u32*)(ap + 8 * 400);
                    a[mt][2] = *(const u32*)(ap + 16);
                    a[mt][3] = *(const u32*)(ap + 8 * 400 + 16);
                }
                u32 b[8][2];
                #pragma unroll
                for (int nt = 0; nt < 8; nt++) {
                    const char* bp = Bsm + (warpCol + nt * 8 + (lane >> 2)) * 400
                                   + (kk + (lane & 3) * 2) * 2;
                    b[nt][0] = *(const u32*)(bp);
                    b[nt][1] = *(const u32*)(bp + 16);
                }
                #pragma unroll
                for (int mt = 0; mt < 2; mt++)
                    #pragma unroll
                    for (int nt = 0; nt < 8; nt++)
                        mma16816(acc[mt][nt][0], acc[mt][nt][1], acc[mt][nt][2], acc[mt][nt][3],
                                 a[mt][0], a[mt][1], a[mt][2], a[mt][3], b[nt][0], b[nt][1]);
            }
        }
    }

    // ---- epilogue ----
    #pragma unroll
    for (int mt = 0; mt < 2; mt++) {
        int r0 = m0 + warpRow + mt * 16 + (lane >> 2);
        #pragma unroll
        for (int nt = 0; nt < 8; nt++) {
            int gc = n0 + warpCol + nt * 8 + (lane & 3) * 2;
            if (gc >= NT) continue;
            float* o;
            const float* bs;
            int Nn, cc;
            if (gc < N1) { o = out1; bs = bias1; Nn = N1; cc = gc; }
            else         { o = out2; bs = bias2; Nn = N2; cc = gc - N1; }
            float bv0 = 0.f, bv1 = 0.f;
            if (bs != 0) { bv0 = bs[cc]; bv1 = bs[cc + 1]; }
            if (r0 < M) {
                float2 w = make_float2(acc[mt][nt][0] + bv0, acc[mt][nt][1] + bv1);
                *(float2*)(o + (size_t)r0 * Nn + cc) = w;
            }
            if (r0 + 8 < M) {
                float2 w = make_float2(acc[mt][nt][2] + bv0, acc[mt][nt][3] + bv1);
                *(float2*)(o + (size_t)(r0 + 8) * Nn + cc) = w;
            }
        }
    }
}

// ---------------- init ----------------
__global__ void init_kernel() {
    int i0 = blockIdx.x * blockDim.x + threadIdx.x;
    int stride = gridDim.x * blockDim.x;
    for (int i = i0; i < N_; i += stride) {
        d_cnt_row[i] = 0;
        d_cnt_col[i] = 0;
    }
    for (int i = i0; i < G_ * C_; i += stride) d_gmax[i] = ENC_NEG_INF;
}

__global__ void cnt_kernel(const int* __restrict__ row, const int* __restrict__ col) {
    int e = blockIdx.x * blockDim.x + threadIdx.x;
    if (e < E_) {
        atomicAdd(&d_cnt_row[row[e]], 1);
        atomicAdd(&d_cnt_col[col[e]], 1);
    }
}

__global__ __launch_bounds__(256) void scan_kernel() {
    __shared__ int warpsums[8];
    __shared__ int s_carry;
    int tid = threadIdx.x;
    const int* cnt = (blockIdx.x == 0) ? d_cnt_row : d_cnt_col;
    int* ptr       = (blockIdx.x == 0) ? d_rowptr  : d_colptr;
    if (tid == 0) s_carry = 0;
    __syncthreads();
    for (int base = 0; base < N_; base += 256) {
        int v = (base + tid < N_) ? cnt[base + tid] : 0;
        int x = v;
        #pragma unroll
        for (int o = 1; o < 32; o <<= 1) {
            int y = __shfl_up_sync(0xffffffffu, x, o);
            if ((tid & 31) >= o) x += y;
        }
        if ((tid & 31) == 31) warpsums[tid >> 5] = x;
        __syncthreads();
        if (tid < 8) {
            int w = warpsums[tid];
            #pragma unroll
            for (int o = 1; o < 8; o <<= 1) {
                int y = __shfl_up_sync(0xffu, w, o);
                if (tid >= o) w += y;
            }
            warpsums[tid] = w;
        }
        __syncthreads();
        int prev = (tid >= 32) ? warpsums[(tid >> 5) - 1] : 0;
        if (base + tid < N_) ptr[base + tid] = s_carry + prev + x - v;
        __syncthreads();
        if (tid == 0) s_carry += warpsums[7];
        __syncthreads();
    }
    if (tid == 0) ptr[N_] = s_carry;
}

__global__ void copycur_kernel() {
    int i = blockIdx.x * blockDim.x + threadIdx.x;
    if (i < N_) {
        d_rowcur[i] = d_rowptr[i];
        d_colcur[i] = d_colptr[i];
    }
}

__global__ void fill_kernel(const int* __restrict__ row, const int* __restrict__ col) {
    int e = blockIdx.x * blockDim.x + threadIdx.x;
    if (e >= E_) return;
    int j = col[e];
    int p = atomicAdd(&d_rowcur[row[e]], 1);
    d_rowe[p] = e;
    d_rowj[p] = j;
    int q = atomicAdd(&d_colcur[j], 1);
    d_cole[q] = e;
}

// ---------------- self-loop attr projection: CSR gather mean ----------------
__global__ __launch_bounds__(320) void lep_kernel() {
    int n = blockIdx.x;
    int tid = threadIdx.x;
    int beg = d_colptr[n];
    int end = d_colptr[n + 1];
    float s = 0.f;
    if (tid < HC_) {
        for (int idx = beg; idx < end; idx++)
            s += d_ep1[(size_t)d_cole[idx] * HC_ + tid];
    } else {
        int c = tid - HC_;
        for (int idx = beg; idx < end; idx++)
            s += d_ep2[(size_t)d_cole[idx] * C_ + c];
    }
    float inv = 1.0f / (float)max(end - beg, 1);
    if (tid < HC_) d_lep1[(size_t)n * HC_ + tid] = s * inv;
    else           d_lep2[(size_t)n * C_ + (tid - HC_)] = s * inv;
}

// ---------------- layer 1 attention: warp per (node, head) — no barriers ----------------
__global__ __launch_bounds__(256) void att1_kernel(const float* __restrict__ att,
                                                   const float* __restrict__ bias) {
    int w = (blockIdx.x * blockDim.x + threadIdx.x) >> 5;
    int lane = threadIdx.x & 31;
    int i = w >> 2;
    int h = w & 3;
    if (i >= N_) return;
    const int off = h * 64;

    float2 xr = ((const float2*)(d_xr1 + (size_t)i * HC_ + off))[lane];
    float2 at = ((const float2*)(att + off))[lane];

    int beg = d_rowptr[i];
    int end = d_rowptr[i + 1];
    float m = -CUDART_INF_F;
    float den = 0.f;
    float accx = 0.f;
    float accy = 0.f;

    float2 xlv, epv;
    if (beg < end) {
        int e = d_rowe[beg];
        int j = d_rowj[beg];
        xlv = ((const float2*)(d_xl1 + (size_t)j * HC_ + off))[lane];
        epv = ((const float2*)(d_ep1 + (size_t)e * HC_ + off))[lane];
    } else {
        xlv = ((const float2*)(d_xl1 + (size_t)i * HC_ + off))[lane];
        epv = ((const float2*)(d_lep1 + (size_t)i * HC_ + off))[lane];
    }

    for (int idx = beg; idx <= end; idx++) {
        float2 xl = xlv;
        float2 e2 = epv;
        int nxt = idx + 1;
        if (nxt < end) {
            int e = d_rowe[nxt];
            int j = d_rowj[nxt];
            xlv = ((const float2*)(d_xl1 + (size_t)j * HC_ + off))[lane];
            epv = ((const float2*)(d_ep1 + (size_t)e * HC_ + off))[lane];
        } else if (nxt == end) {
            xlv = ((const float2*)(d_xl1 + (size_t)i * HC_ + off))[lane];
            epv = ((const float2*)(d_lep1 + (size_t)i * HC_ + off))[lane];
        }

        float v0 = xl.x + xr.x + e2.x;
        v0 = v0 > 0.f ? v0 : 0.2f * v0;
        float v1 = xl.y + xr.y + e2.y;
        v1 = v1 > 0.f ? v1 : 0.2f * v1;
        float t = v0 * at.x + v1 * at.y;
        #pragma unroll
        for (int o = 1; o < 32; o <<= 1) t += __shfl_xor_sync(0xffffffffu, t, o);

        float mn = fmaxf(m, t);
        float sc = __expf(m - mn);
        float ex = __expf(t - mn);
        den = den * sc + ex;
        accx = accx * sc + xl.x * ex;
        accy = accy * sc + xl.y * ex;
        m = mn;
    }

    float2 bv = ((const float2*)(bias + off))[lane];
    float o0 = accx / den + bv.x;
    float o1 = accy / den + bv.y;
    o0 = o0 > 0.f ? o0 : 0.01f * o0;
    o1 = o1 > 0.f ? o1 : 0.01f * o1;
    ((float2*)(d_h1 + (size_t)i * HC_ + off))[lane] = make_float2(o0, o1);
}

// ---------------- layer 2 attention: warp per node ----------------
__global__ __launch_bounds__(256) void att2_kernel(const float* __restrict__ att,
                                                   const float* __restrict__ bias) {
    int i = (blockIdx.x * blockDim.x + threadIdx.x) >> 5;
    int lane = threadIdx.x & 31;
    if (i >= N_) return;

    float2 xr = ((const float2*)(d_xr2 + (size_t)i * C_))[lane];
    float2 at = ((const float2*)att)[lane];

    int beg = d_rowptr[i];
    int end = d_rowptr[i + 1];
    float m = -CUDART_INF_F;
    float den = 0.f;
    float accx = 0.f;
    float accy = 0.f;

    float2 xlv, epv;
    if (beg < end) {
        int e = d_rowe[beg];
        int j = d_rowj[beg];
        xlv = ((const float2*)(d_xl2 + (size_t)j * C_))[lane];
        epv = ((const float2*)(d_ep2 + (size_t)e * C_))[lane];
    } else {
        xlv = ((const float2*)(d_xl2 + (size_t)i * C_))[lane];
        epv = ((const float2*)(d_lep2 + (size_t)i * C_))[lane];
    }

    for (int idx = beg; idx <= end; idx++) {
        float2 xl = xlv;
        float2 e2 = epv;
        int nxt = idx + 1;
        if (nxt < end) {
            int e = d_rowe[nxt];
            int j = d_rowj[nxt];
            xlv = ((const float2*)(d_xl2 + (size_t)j * C_))[lane];
            epv = ((const float2*)(d_ep2 + (size_t)e * C_))[lane];
        } else if (nxt == end) {
            xlv = ((const float2*)(d_xl2 + (size_t)i * C_))[lane];
            epv = ((const float2*)(d_lep2 + (size_t)i * C_))[lane];
        }

        float v0 = xl.x + xr.x + e2.x;
        v0 = v0 > 0.f ? v0 : 0.2f * v0;
        float v1 = xl.y + xr.y + e2.y;
        v1 = v1 > 0.f ? v1 : 0.2f * v1;
        float t = v0 * at.x + v1 * at.y;
        #pragma unroll
        for (int o = 1; o < 32; o <<= 1) t += __shfl_xor_sync(0xffffffffu, t, o);

        float mn = fmaxf(m, t);
        float sc = __expf(m - mn);
        float ex = __expf(t - mn);
        den = den * sc + ex;
        accx = accx * sc + xl.x * ex;
        accy = accy * sc + xl.y * ex;
        m = mn;
    }

    float2 bv = ((const float2*)bias)[lane];
    float o0 = accx / den + bv.x;
    float o1 = accy / den + bv.y;
    o0 = o0 > 0.f ? o0 : 0.01f * o0;
    o1 = o1 > 0.f ? o1 : 0.01f * o1;
    ((float2*)(d_h2 + (size_t)i * C_))[lane] = make_float2(o0, o1);
}

// ---------------- global max pool ----------------
__global__ void pool_kernel(const int* __restrict__ batch) {
    int idx = blockIdx.x * blockDim.x + threadIdx.x;
    if (idx >= N_ * C_) return;
    int n = idx >> 6;
    int c = idx & 63;
    atomicMax(&d_gmax[batch[n] * C_ + c], fenc(d_h2[idx]));
}

// ---------------- layernorm + classifier ----------------
__global__ void final_kernel(const float* __restrict__ ln_g, const float* __restrict__ ln_b,
                             const float* __restrict__ clf_W, const float* __restrict__ clf_b,
                             float* __restrict__ out, int out_size) {
    int g = blockIdx.x;
    int tid = threadIdx.x;
    __shared__ float sg[C_];
    __shared__ float sgn[C_];
    __shared__ float s_mu, s_rstd;
    if (tid < C_) sg[tid] = fdec(d_gmax[g * C_ + tid]);
    __syncthreads();
    if (tid == 0) {
        float m = 0.f;
        for (int c = 0; c < C_; c++) m += sg[c];
        m *= (1.0f / C_);
        float v = 0.f;
        for (int c = 0; c < C_; c++) {
            float dd = sg[c] - m;
            v += dd * dd;
        }
        v *= (1.0f / C_);
        s_mu = m;
        s_rstd = rsqrtf(v + 1e-5f);
    }
    __syncthreads();
    if (tid < C_) {
        float gn = (sg[tid] - s_mu) * s_rstd * ln_g[tid] + ln_b[tid];
        sgn[tid] = gn;
        if (out_size >= G_ * NC_ + G_ * C_) out[G_ * NC_ + g * C_ + tid] = gn;
    }
    __syncthreads();
    for (int o = tid; o < NC_; o += blockDim.x) {
        float s = clf_b[o];
        #pragma unroll 8
        for (int c = 0; c < C_; c++) s += sgn[c] * clf_W[c * NC_ + o];
        out[g * NC_ + o] = s;
    }
}

// ---------------- launch ----------------
extern "C" void kernel_launch(void* const* d_in, const int* in_sizes, int n_in,
                              void* d_out, int out_size) {
    const float* x     = (const float*)d_in[0];
    const int*   ei    = (const int*)  d_in[1];
    const float* ea    = (const float*)d_in[2];
    const int*   batch = (const int*)  d_in[3];
    const float* W1l = (const float*)d_in[4];
    const float* b1l  = (const float*)d_in[5];
    const float* W1r = (const float*)d_in[6];
    const float* b1r  = (const float*)d_in[7];
    const float* W1e = (const float*)d_in[8];
    const float* att1 = (const float*)d_in[9];
    const float* bias1 = (const float*)d_in[10];
    const float* W2l = (const float*)d_in[11];
    const float* b2l  = (const float*)d_in[12];
    const float* W2r = (const float*)d_in[13];
    const float* b2r  = (const float*)d_in[14];
    const float* W2e = (const float*)d_in[15];
    const float* att2 = (const float*)d_in[16];
    const float* bias2 = (const float*)d_in[17];
    const float* ln_g = (const float*)d_in[18];
    const float* ln_b = (const float*)d_in[19];
    const float* clfW = (const float*)d_in[20];
    const float* clfb = (const float*)d_in[21];

    const int* row = ei;
    const int* col = ei + E_;
    float* out = (float*)d_out;

    float *p_xl1, *p_xr1, *p_ep1, *p_ep2, *p_h1, *p_xl2, *p_xr2;
    cudaGetSymbolAddress((void**)&p_xl1, d_xl1);
    cudaGetSymbolAddress((void**)&p_xr1, d_xr1);
    cudaGetSymbolAddress((void**)&p_ep1, d_ep1);
    cudaGetSymbolAddress((void**)&p_ep2, d_ep2);
    cudaGetSymbolAddress((void**)&p_h1,  d_h1);
    cudaGetSymbolAddress((void**)&p_xl2, d_xl2);
    cudaGetSymbolAddress((void**)&p_xr2, d_xr2);
    __nv_bfloat16 *pBep_hi, *pBep_lo, *pBx_hi, *pBx_lo, *pBh_hi, *pBh_lo;
    cudaGetSymbolAddress((void**)&pBep_hi, d_Bep_hi);
    cudaGetSymbolAddress((void**)&pBep_lo, d_Bep_lo);
    cudaGetSymbolAddress((void**)&pBx_hi,  d_Bx_hi);
    cudaGetSymbolAddress((void**)&pBx_lo,  d_Bx_lo);
    cudaGetSymbolAddress((void**)&pBh_hi,  d_Bh_hi);
    cudaGetSymbolAddress((void**)&pBh_lo,  d_Bh_lo);

    const int SMEM_MMA = 102400;
    cudaFuncSetAttribute(mma_gemm, cudaFuncAttributeMaxDynamicSharedMemorySize, SMEM_MMA);

    // Launch order places the ep mma_gemm at index 3 (the slot ncu captures).
    prep_weights<<<(512 * 512 + 255) / 256, 256>>>(W1e, W2e, W1l, W1r, W2l, W2r);   // 0
    init_kernel<<<256, 256>>>();                                                     // 1
    cnt_kernel<<<(E_ + 255) / 256, 256>>>(row, col);                                 // 2
    // ep GEMM: grid (NY=3 fast, MX=1563 slow) for A L2 reuse                        // 3
    mma_gemm<<<dim3(3, (E_ + 127) / 128), 256, SMEM_MMA>>>(
        ea, 384, E_, pBep_hi, pBep_lo, p_ep1, p_ep2, (const float*)0, (const float*)0, 256, 64);
    scan_kernel<<<2, 256>>>();                                                       // 4
    copycur_kernel<<<(N_ + 255) / 256, 256>>>();                                     // 5
    fill_kernel<<<(E_ + 255) / 256, 256>>>(row, col);                                // 6
    mma_gemm<<<dim3(4, (N_ + 127) / 128), 256, SMEM_MMA>>>(                          // 7
        x, 512, N_, pBx_hi, pBx_lo, p_xl1, p_xr1, b1l, b1r, 256, 256);

    // self-loop attrs (gather by col)
    lep_kernel<<<N_, 320>>>();

    // layer 1 attention (warp per node-head)
    att1_kernel<<<(N_ * H_ * 32 + 255) / 256, 256>>>(att1, bias1);

    // layer 2 transforms
    mma_gemm<<<dim3(1, (N_ + 127) / 128), 256, SMEM_MMA>>>(
        p_h1, 256, N_, pBh_hi, pBh_lo, p_xl2, p_xr2, b2l, b2r, 64, 64);

    // layer 2 attention
    att2_kernel<<<(N_ * 32 + 255) / 256, 256>>>(att2, bias2);

    pool_kernel<<<(N_ * C_ + 255) / 256, 256>>>(batch);
    final_kernel<<<G_, 256>>>(ln_g, ln_b, clfW, clfb, out, out_size);
}

// round 15
// speedup vs baseline: 1.4458x; 1.0981x over previous
#include <cuda_runtime.h>
#include <cuda_bf16.h>
#include <math_constants.h>

typedef unsigned int u32;

// ---------------- problem constants ----------------
constexpr int N_  = 20000;
constexpr int E_  = 200000;
constexpr int H_  = 4;
constexpr int C_  = 64;
constexpr int G_  = 64;
constexpr int NC_ = 751;
constexpr int HC_ = H_ * C_;       // 256

// ---------------- scratch (device globals; no allocation allowed) ----------------
__device__ float    d_xl1[(size_t)N_ * HC_];
__device__ float    d_xr1[(size_t)N_ * HC_];
__device__ float    d_ep1[(size_t)E_ * HC_];
__device__ float    d_ep2[(size_t)E_ * C_];
__device__ float    d_lep1[(size_t)N_ * HC_];
__device__ float    d_lep2[(size_t)N_ * C_];
__device__ float    d_h1[(size_t)N_ * HC_];
__device__ float    d_xl2[(size_t)N_ * C_];
__device__ float    d_xr2[(size_t)N_ * C_];
__device__ unsigned d_gmax[G_ * C_];

// split-bf16 weight buffers: [N rows][K cols] K-major (transposed from input [K][N])
__device__ __nv_bfloat16 d_Bep_hi[320 * 384];
__device__ __nv_bfloat16 d_Bep_lo[320 * 384];
__device__ __nv_bfloat16 d_Bx_hi[512 * 512];
__device__ __nv_bfloat16 d_Bx_lo[512 * 512];
__device__ __nv_bfloat16 d_Bh_hi[128 * 256];
__device__ __nv_bfloat16 d_Bh_lo[128 * 256];

// CSR structures
__device__ int d_cnt_row[N_];
__device__ int d_cnt_col[N_];
__device__ int d_rowptr[N_ + 1];
__device__ int d_colptr[N_ + 1];
__device__ int d_rowcur[N_];
__device__ int d_colcur[N_];
__device__ int d_rowe[E_];
__device__ int d_rowj[E_];
__device__ int d_cole[E_];

// ---------------- helpers ----------------
__device__ __forceinline__ unsigned fenc(float f) {
    unsigned u = __float_as_uint(f);
    return (u & 0x80000000u) ? ~u : (u | 0x80000000u);
}
__device__ __forceinline__ float fdec(unsigned u) {
    u = (u & 0x80000000u) ? (u & 0x7fffffffu) : ~u;
    return __uint_as_float(u);
}
constexpr unsigned ENC_NEG_INF = 0x007fffffu;

__device__ __forceinline__ u32 pack_bf16(float x, float y) {
    unsigned short lo = __bfloat16_as_ushort(__float2bfloat16(x));
    unsigned short hi = __bfloat16_as_ushort(__float2bfloat16(y));
    return (u32)lo | ((u32)hi << 16);
}
__device__ __forceinline__ float bf_res(float x) {
    return x - __bfloat162float(__float2bfloat16(x));
}

__device__ __forceinline__ void mma16816(float& c0, float& c1, float& c2, float& c3,
                                         u32 a0, u32 a1, u32 a2, u32 a3,
                                         u32 b0, u32 b1) {
    asm volatile(
        "mma.sync.aligned.m16n8k16.row.col.f32.bf16.bf16.f32 "
        "{%0,%1,%2,%3}, {%4,%5,%6,%7}, {%8,%9}, {%0,%1,%2,%3};"
        : "+f"(c0), "+f"(c1), "+f"(c2), "+f"(c3)
        : "r"(a0), "r"(a1), "r"(a2), "r"(a3), "r"(b0), "r"(b1));
}

// ---------------- weight prep: transpose + bf16 split ----------------
__global__ void prep_weights(const float* __restrict__ W1e, const float* __restrict__ W2e,
                             const float* __restrict__ W1l, const float* __restrict__ W1r,
                             const float* __restrict__ W2l, const float* __restrict__ W2r) {
    int idx = blockIdx.x * blockDim.x + threadIdx.x;
    if (idx < 320 * 384) {
        int n = idx / 384;
        int k = idx % 384;
        float v = (n < 256) ? W1e[k * 256 + n] : W2e[k * 64 + (n - 256)];
        __nv_bfloat16 h = __float2bfloat16(v);
        d_Bep_hi[idx] = h;
        d_Bep_lo[idx] = __float2bfloat16(v - __bfloat162float(h));
    }
    if (idx < 512 * 512) {
        int n = idx >> 9;
        int k = idx & 511;
        float v = (n < 256) ? W1l[k * 256 + n] : W1r[k * 256 + (n - 256)];
        __nv_bfloat16 h = __float2bfloat16(v);
        d_Bx_hi[idx] = h;
        d_Bx_lo[idx] = __float2bfloat16(v - __bfloat162float(h));
    }
    if (idx < 128 * 256) {
        int n = idx >> 8;
        int k = idx & 255;
        float v = (n < 64) ? W2l[k * 64 + n] : W2r[k * 64 + (n - 64)];
        __nv_bfloat16 h = __float2bfloat16(v);
        d_Bh_hi[idx] = h;
        d_Bh_lo[idx] = __float2bfloat16(v - __bfloat162float(h));
    }
}

// ---------------- mma.sync split-bf16 GEMM (frozen R14 version — DO NOT TOUCH) ----------------
__global__ __launch_bounds__(256) void mma_gemm(
    const float* __restrict__ A, int K, int M,
    const __nv_bfloat16* __restrict__ Bhi, const __nv_bfloat16* __restrict__ Blo,
    float* __restrict__ out1, float* __restrict__ out2,
    const float* __restrict__ bias1, const float* __restrict__ bias2,
    int N1, int N2)
{
    extern __shared__ char smem[];
    char* Asm = smem;            // 128 rows * 400B = 51200
    char* Bsm = smem + 51200;    // 51200

    const int tid = threadIdx.x;
    const int wid = tid >> 5;
    const int lane = tid & 31;
    const int m0 = blockIdx.y * 128;   // row-block: slow dimension
    const int n0 = blockIdx.x * 128;   // col-block: fast dimension (L2 reuse of A)
    const int NT = N1 + N2;
    const int warpRow = (wid & 3) * 32;
    const int warpCol = (wid >> 2) * 64;
    const bool warpActive = (n0 + warpCol) < NT;   // warp-uniform: skip dead columns

    float acc[2][8][4];
    #pragma unroll
    for (int i = 0; i < 2; i++)
        #pragma unroll
        for (int j = 0; j < 8; j++)
            #pragma unroll
            for (int q = 0; q < 4; q++)
                acc[i][j][q] = 0.f;

    for (int k0 = 0; k0 < K; k0 += 64) {
        __syncthreads();
        // ---- A chunk: 128 rows x 64 fp32 -> bf16 hi/lo concat ----
        #pragma unroll
        for (int it = 0; it < 8; it++) {
            int idx = tid + it * 256;
            int r = idx >> 4;
            int q = idx & 15;
            float4 v = make_float4(0.f, 0.f, 0.f, 0.f);
            if (m0 + r < M) v = *(const float4*)(A + (size_t)(m0 + r) * K + k0 + q * 4);
            u32 h0 = pack_bf16(v.x, v.y);
            u32 h1 = pack_bf16(v.z, v.w);
            u32 l0 = pack_bf16(bf_res(v.x), bf_res(v.y));
            u32 l1 = pack_bf16(bf_res(v.z), bf_res(v.w));
            char* rowp = Asm + r * 400 + q * 8;
            *(uint2*)(rowp)       = make_uint2(h0, h1);
            *(uint2*)(rowp + 128) = make_uint2(l0, l1);
            *(uint2*)(rowp + 256) = make_uint2(h0, h1);
        }
        // ---- B chunk: 128 rows x 64 bf16 hi/lo concat [hi|hi|lo] ----
        #pragma unroll
        for (int it = 0; it < 4; it++) {
            int idx = tid + it * 256;
            int n = idx >> 3;
            int q = idx & 7;
            uint4 vh = make_uint4(0u, 0u, 0u, 0u);
            uint4 vl = vh;
            if (n0 + n < NT) {
                vh = *(const uint4*)(Bhi + (size_t)(n0 + n) * K + k0 + q * 8);
                vl = *(const uint4*)(Blo + (size_t)(n0 + n) * K + k0 + q * 8);
            }
            char* rowp = Bsm + n * 400 + q * 16;
            *(uint4*)(rowp)       = vh;
            *(uint4*)(rowp + 128) = vh;
            *(uint4*)(rowp + 256) = vl;
        }
        __syncthreads();

        // ---- mma over 192 concat columns (plain LDS fragments; compiler-scheduled) ----
        if (warpActive) {
            #pragma unroll
            for (int kk = 0; kk < 192; kk += 16) {
                u32 a[2][4];
                #pragma unroll
                for (int mt = 0; mt < 2; mt++) {
                    const char* ap = Asm + (warpRow + mt * 16 + (lane >> 2)) * 400
                                   + (kk + (lane & 3) * 2) * 2;
                    a[mt][0] = *(const u32*)(ap);
                    a[mt][1] = *(const u32*)(ap + 8 * 400);
                    a[mt][2] = *(const u32*)(ap + 16);
                    a[mt][3] = *(const u32*)(ap + 8 * 400 + 16);
                }
                u32 b[8][2];
                #pragma unroll
                for (int nt = 0; nt < 8; nt++) {
                    const char* bp = Bsm + (warpCol + nt * 8 + (lane >> 2)) * 400
                                   + (kk + (lane & 3) * 2) * 2;
                    b[nt][0] = *(const u32*)(bp);
                    b[nt][1] = *(const u32*)(bp + 16);
                }
                #pragma unroll
                for (int mt = 0; mt < 2; mt++)
                    #pragma unroll
                    for (int nt = 0; nt < 8; nt++)
                        mma16816(acc[mt][nt][0], acc[mt][nt][1], acc[mt][nt][2], acc[mt][nt][3],
                                 a[mt][0], a[mt][1], a[mt][2], a[mt][3], b[nt][0], b[nt][1]);
            }
        }
    }

    // ---- epilogue ----
    #pragma unroll
    for (int mt = 0; mt < 2; mt++) {
        int r0 = m0 + warpRow + mt * 16 + (lane >> 2);
        #pragma unroll
        for (int nt = 0; nt < 8; nt++) {
            int gc = n0 + warpCol + nt * 8 + (lane & 3) * 2;
            if (gc >= NT) continue;
            float* o;
            const float* bs;
            int Nn, cc;
            if (gc < N1) { o = out1; bs = bias1; Nn = N1; cc = gc; }
            else         { o = out2; bs = bias2; Nn = N2; cc = gc - N1; }
            float bv0 = 0.f, bv1 = 0.f;
            if (bs != 0) { bv0 = bs[cc]; bv1 = bs[cc + 1]; }
            if (r0 < M) {
                float2 w = make_float2(acc[mt][nt][0] + bv0, acc[mt][nt][1] + bv1);
                *(float2*)(o + (size_t)r0 * Nn + cc) = w;
            }
            if (r0 + 8 < M) {
                float2 w = make_float2(acc[mt][nt][2] + bv0, acc[mt][nt][3] + bv1);
                *(float2*)(o + (size_t)(r0 + 8) * Nn + cc) = w;
            }
        }
    }
}

// ---------------- init ----------------
__global__ void init_kernel() {
    int i0 = blockIdx.x * blockDim.x + threadIdx.x;
    int stride = gridDim.x * blockDim.x;
    for (int i = i0; i < N_; i += stride) {
        d_cnt_row[i] = 0;
        d_cnt_col[i] = 0;
    }
    for (int i = i0; i < G_ * C_; i += stride) d_gmax[i] = ENC_NEG_INF;
}

__global__ void cnt_kernel(const int* __restrict__ row, const int* __restrict__ col) {
    int e = blockIdx.x * blockDim.x + threadIdx.x;
    if (e < E_) {
        atomicAdd(&d_cnt_row[row[e]], 1);
        atomicAdd(&d_cnt_col[col[e]], 1);
    }
}

__global__ __launch_bounds__(256) void scan_kernel() {
    __shared__ int warpsums[8];
    __shared__ int s_carry;
    int tid = threadIdx.x;
    const int* cnt = (blockIdx.x == 0) ? d_cnt_row : d_cnt_col;
    int* ptr       = (blockIdx.x == 0) ? d_rowptr  : d_colptr;
    if (tid == 0) s_carry = 0;
    __syncthreads();
    for (int base = 0; base < N_; base += 256) {
        int v = (base + tid < N_) ? cnt[base + tid] : 0;
        int x = v;
        #pragma unroll
        for (int o = 1; o < 32; o <<= 1) {
            int y = __shfl_up_sync(0xffffffffu, x, o);
            if ((tid & 31) >= o) x += y;
        }
        if ((tid & 31) == 31) warpsums[tid >> 5] = x;
        __syncthreads();
        if (tid < 8) {
            int w = warpsums[tid];
            #pragma unroll
            for (int o = 1; o < 8; o <<= 1) {
                int y = __shfl_up_sync(0xffu, w, o);
                if (tid >= o) w += y;
            }
            warpsums[tid] = w;
        }
        __syncthreads();
        int prev = (tid >= 32) ? warpsums[(tid >> 5) - 1] : 0;
        if (base + tid < N_) ptr[base + tid] = s_carry + prev + x - v;
        __syncthreads();
        if (tid == 0) s_carry += warpsums[7];
        __syncthreads();
    }
    if (tid == 0) ptr[N_] = s_carry;
}

__global__ void copycur_kernel() {
    int i = blockIdx.x * blockDim.x + threadIdx.x;
    if (i < N_) {
        d_rowcur[i] = d_rowptr[i];
        d_colcur[i] = d_colptr[i];
    }
}

__global__ void fill_kernel(const int* __restrict__ row, const int* __restrict__ col) {
    int e = blockIdx.x * blockDim.x + threadIdx.x;
    if (e >= E_) return;
    int j = col[e];
    int p = atomicAdd(&d_rowcur[row[e]], 1);
    d_rowe[p] = e;
    d_rowj[p] = j;
    int q = atomicAdd(&d_colcur[j], 1);
    d_cole[q] = e;
}

// ---------------- self-loop attr projection: CSR gather mean (float4 lanes) ----------------
__global__ __launch_bounds__(96) void lep_kernel() {
    int n = blockIdx.x;
    int t = threadIdx.x;
    int beg = d_colptr[n];
    int end = d_colptr[n + 1];
    float inv = 1.0f / (float)max(end - beg, 1);
    if (t < 64) {
        float4 s = make_float4(0.f, 0.f, 0.f, 0.f);
        #pragma unroll 4
        for (int idx = beg; idx < end; idx++) {
            const float4 v = *(const float4*)(d_ep1 + (size_t)d_cole[idx] * HC_ + t * 4);
            s.x += v.x; s.y += v.y; s.z += v.z; s.w += v.w;
        }
        *(float4*)(d_lep1 + (size_t)n * HC_ + t * 4) =
            make_float4(s.x * inv, s.y * inv, s.z * inv, s.w * inv);
    } else if (t < 80) {
        int c = (t - 64) * 4;
        float4 s = make_float4(0.f, 0.f, 0.f, 0.f);
        #pragma unroll 4
        for (int idx = beg; idx < end; idx++) {
            const float4 v = *(const float4*)(d_ep2 + (size_t)d_cole[idx] * C_ + c);
            s.x += v.x; s.y += v.y; s.z += v.z; s.w += v.w;
        }
        *(float4*)(d_lep2 + (size_t)n * C_ + c) =
            make_float4(s.x * inv, s.y * inv, s.z * inv, s.w * inv);
    }
}

// ---------------- layer 1 attention: warp per (node, head-pair), float4 lanes ----------------
// Lane L covers 4 channels at float offset hp*64 + L*4 (heads hp, hp+1).
// Per-head logit reduce = xor shuffles 1,2,4,8 (confined to 16-lane halves).
__global__ __launch_bounds__(256) void att1_kernel(const float* __restrict__ att,
                                                   const float* __restrict__ bias) {
    int w = (blockIdx.x * blockDim.x + threadIdx.x) >> 5;
    int lane = threadIdx.x & 31;
    int i = w >> 1;
    if (i >= N_) return;
    const int off = (w & 1) * 128 + lane * 4;   // float offset within the 256-wide row

    float4 xr = *(const float4*)(d_xr1 + (size_t)i * HC_ + off);
    float4 at = *(const float4*)(att + off);

    int beg = d_rowptr[i];
    int end = d_rowptr[i + 1];
    float m = -CUDART_INF_F;
    float den = 0.f;
    float4 acc = make_float4(0.f, 0.f, 0.f, 0.f);

    float4 xlv, epv;
    if (beg < end) {
        int e = d_rowe[beg];
        int j = d_rowj[beg];
        xlv = *(const float4*)(d_xl1 + (size_t)j * HC_ + off);
        epv = *(const float4*)(d_ep1 + (size_t)e * HC_ + off);
    } else {
        xlv = *(const float4*)(d_xl1 + (size_t)i * HC_ + off);
        epv = *(const float4*)(d_lep1 + (size_t)i * HC_ + off);
    }

    for (int idx = beg; idx <= end; idx++) {
        float4 xl = xlv;
        float4 e4 = epv;
        int nxt = idx + 1;
        if (nxt < end) {
            int e = d_rowe[nxt];
            int j = d_rowj[nxt];
            xlv = *(const float4*)(d_xl1 + (size_t)j * HC_ + off);
            epv = *(const float4*)(d_ep1 + (size_t)e * HC_ + off);
        } else if (nxt == end) {
            xlv = *(const float4*)(d_xl1 + (size_t)i * HC_ + off);
            epv = *(const float4*)(d_lep1 + (size_t)i * HC_ + off);
        }

        float v0 = xl.x + xr.x + e4.x; v0 = v0 > 0.f ? v0 : 0.2f * v0;
        float v1 = xl.y + xr.y + e4.y; v1 = v1 > 0.f ? v1 : 0.2f * v1;
        float v2 = xl.z + xr.z + e4.z; v2 = v2 > 0.f ? v2 : 0.2f * v2;
        float v3 = xl.w + xr.w + e4.w; v3 = v3 > 0.f ? v3 : 0.2f * v3;
        float t = v0 * at.x + v1 * at.y + v2 * at.z + v3 * at.w;
        #pragma unroll
        for (int o = 1; o < 16; o <<= 1) t += __shfl_xor_sync(0xffffffffu, t, o);

        float mn = fmaxf(m, t);
        float sc = __expf(m - mn);
        float ex = __expf(t - mn);
        den = den * sc + ex;
        acc.x = acc.x * sc + xl.x * ex;
        acc.y = acc.y * sc + xl.y * ex;
        acc.z = acc.z * sc + xl.z * ex;
        acc.w = acc.w * sc + xl.w * ex;
        m = mn;
    }

    float4 bv = *(const float4*)(bias + off);
    float r = 1.0f / den;
    float o0 = acc.x * r + bv.x;
    float o1 = acc.y * r + bv.y;
    float o2 = acc.z * r + bv.z;
    float o3 = acc.w * r + bv.w;
    o0 = o0 > 0.f ? o0 : 0.01f * o0;
    o1 = o1 > 0.f ? o1 : 0.01f * o1;
    o2 = o2 > 0.f ? o2 : 0.01f * o2;
    o3 = o3 > 0.f ? o3 : 0.01f * o3;
    *(float4*)(d_h1 + (size_t)i * HC_ + off) = make_float4(o0, o1, o2, o3);
}

// ---------------- layer 2 attention: warp per node; fused global max pool ----------------
__global__ __launch_bounds__(256) void att2_kernel(const float* __restrict__ att,
                                                   const float* __restrict__ bias,
                                                   const int* __restrict__ batch) {
    int i = (blockIdx.x * blockDim.x + threadIdx.x) >> 5;
    int lane = threadIdx.x & 31;
    if (i >= N_) return;

    float2 xr = ((const float2*)(d_xr2 + (size_t)i * C_))[lane];
    float2 at = ((const float2*)att)[lane];

    int beg = d_rowptr[i];
    int end = d_rowptr[i + 1];
    float m = -CUDART_INF_F;
    float den = 0.f;
    float accx = 0.f;
    float accy = 0.f;

    float2 xlv, epv;
    if (beg < end) {
        int e = d_rowe[beg];
        int j = d_rowj[beg];
        xlv = ((const float2*)(d_xl2 + (size_t)j * C_))[lane];
        epv = ((const float2*)(d_ep2 + (size_t)e * C_))[lane];
    } else {
        xlv = ((const float2*)(d_xl2 + (size_t)i * C_))[lane];
        epv = ((const float2*)(d_lep2 + (size_t)i * C_))[lane];
    }

    for (int idx = beg; idx <= end; idx++) {
        float2 xl = xlv;
        float2 e2 = epv;
        int nxt = idx + 1;
        if (nxt < end) {
            int e = d_rowe[nxt];
            int j = d_rowj[nxt];
            xlv = ((const float2*)(d_xl2 + (size_t)j * C_))[lane];
            epv = ((const float2*)(d_ep2 + (size_t)e * C_))[lane];
        } else if (nxt == end) {
            xlv = ((const float2*)(d_xl2 + (size_t)i * C_))[lane];
            epv = ((const float2*)(d_lep2 + (size_t)i * C_))[lane];
        }

        float v0 = xl.x + xr.x + e2.x;
        v0 = v0 > 0.f ? v0 : 0.2f * v0;
        float v1 = xl.y + xr.y + e2.y;
        v1 = v1 > 0.f ? v1 : 0.2f * v1;
        float t = v0 * at.x + v1 * at.y;
        #pragma unroll
        for (int o = 1; o < 32; o <<= 1) t += __shfl_xor_sync(0xffffffffu, t, o);

        float mn = fmaxf(m, t);
        float sc = __expf(m - mn);
        float ex = __expf(t - mn);
        den = den * sc + ex;
        accx = accx * sc + xl.x * ex;
        accy = accy * sc + xl.y * ex;
        m = mn;
    }

    float2 bv = ((const float2*)bias)[lane];
    float o0 = accx / den + bv.x;
    float o1 = accy / den + bv.y;
    o0 = o0 > 0.f ? o0 : 0.01f * o0;
    o1 = o1 > 0.f ? o1 : 0.01f * o1;

    // fused global max pool (h2 never materialized)
    unsigned gidx = (unsigned)batch[i] * C_ + lane * 2;
    atomicMax(&d_gmax[gidx],     fenc(o0));
    atomicMax(&d_gmax[gidx + 1], fenc(o1));
}

// ---------------- layernorm + classifier ----------------
__global__ void final_kernel(const float* __restrict__ ln_g, const float* __restrict__ ln_b,
                             const float* __restrict__ clf_W, const float* __restrict__ clf_b,
                             float* __restrict__ out, int out_size) {
    int g = blockIdx.x;
    int tid = threadIdx.x;
    __shared__ float sg[C_];
    __shared__ float sgn[C_];
    __shared__ float s_mu, s_rstd;
    if (tid < C_) sg[tid] = fdec(d_gmax[g * C_ + tid]);
    __syncthreads();
    if (tid == 0) {
        float m = 0.f;
        for (int c = 0; c < C_; c++) m += sg[c];
        m *= (1.0f / C_);
        float v = 0.f;
        for (int c = 0; c < C_; c++) {
            float dd = sg[c] - m;
            v += dd * dd;
        }
        v *= (1.0f / C_);
        s_mu = m;
        s_rstd = rsqrtf(v + 1e-5f);
    }
    __syncthreads();
    if (tid < C_) {
        float gn = (sg[tid] - s_mu) * s_rstd * ln_g[tid] + ln_b[tid];
        sgn[tid] = gn;
        if (out_size >= G_ * NC_ + G_ * C_) out[G_ * NC_ + g * C_ + tid] = gn;
    }
    __syncthreads();
    for (int o = tid; o < NC_; o += blockDim.x) {
        float s = clf_b[o];
        #pragma unroll 8
        for (int c = 0; c < C_; c++) s += sgn[c] * clf_W[c * NC_ + o];
        out[g * NC_ + o] = s;
    }
}

// ---------------- launch ----------------
extern "C" void kernel_launch(void* const* d_in, const int* in_sizes, int n_in,
                              void* d_out, int out_size) {
    const float* x     = (const float*)d_in[0];
    const int*   ei    = (const int*)  d_in[1];
    const float* ea    = (const float*)d_in[2];
    const int*   batch = (const int*)  d_in[3];
    const float* W1l = (const float*)d_in[4];
    const float* b1l  = (const float*)d_in[5];
    const float* W1r = (const float*)d_in[6];
    const float* b1r  = (const float*)d_in[7];
    const float* W1e = (const float*)d_in[8];
    const float* att1 = (const float*)d_in[9];
    const float* bias1 = (const float*)d_in[10];
    const float* W2l = (const float*)d_in[11];
    const float* b2l  = (const float*)d_in[12];
    const float* W2r = (const float*)d_in[13];
    const float* b2r  = (const float*)d_in[14];
    const float* W2e = (const float*)d_in[15];
    const float* att2 = (const float*)d_in[16];
    const float* bias2 = (const float*)d_in[17];
    const float* ln_g = (const float*)d_in[18];
    const float* ln_b = (const float*)d_in[19];
    const float* clfW = (const float*)d_in[20];
    const float* clfb = (const float*)d_in[21];

    const int* row = ei;
    const int* col = ei + E_;
    float* out = (float*)d_out;

    float *p_xl1, *p_xr1, *p_ep1, *p_ep2, *p_h1, *p_xl2, *p_xr2;
    cudaGetSymbolAddress((void**)&p_xl1, d_xl1);
    cudaGetSymbolAddress((void**)&p_xr1, d_xr1);
    cudaGetSymbolAddress((void**)&p_ep1, d_ep1);
    cudaGetSymbolAddress((void**)&p_ep2, d_ep2);
    cudaGetSymbolAddress((void**)&p_h1,  d_h1);
    cudaGetSymbolAddress((void**)&p_xl2, d_xl2);
    cudaGetSymbolAddress((void**)&p_xr2, d_xr2);
    __nv_bfloat16 *pBep_hi, *pBep_lo, *pBx_hi, *pBx_lo, *pBh_hi, *pBh_lo;
    cudaGetSymbolAddress((void**)&pBep_hi, d_Bep_hi);
    cudaGetSymbolAddress((void**)&pBep_lo, d_Bep_lo);
    cudaGetSymbolAddress((void**)&pBx_hi,  d_Bx_hi);
    cudaGetSymbolAddress((void**)&pBx_lo,  d_Bx_lo);
    cudaGetSymbolAddress((void**)&pBh_hi,  d_Bh_hi);
    cudaGetSymbolAddress((void**)&pBh_lo,  d_Bh_lo);

    const int SMEM_MMA = 102400;
    cudaFuncSetAttribute(mma_gemm, cudaFuncAttributeMaxDynamicSharedMemorySize, SMEM_MMA);

    // Launch order places the ep mma_gemm at index 3 (the slot ncu captures).
    prep_weights<<<(512 * 512 + 255) / 256, 256>>>(W1e, W2e, W1l, W1r, W2l, W2r);   // 0
    init_kernel<<<256, 256>>>();                                                     // 1
    cnt_kernel<<<(E_ + 255) / 256, 256>>>(row, col);                                 // 2
    // ep GEMM: grid (NY=3 fast, MX=1563 slow) for A L2 reuse                        // 3
    mma_gemm<<<dim3(3, (E_ + 127) / 128), 256, SMEM_MMA>>>(
        ea, 384, E_, pBep_hi, pBep_lo, p_ep1, p_ep2, (const float*)0, (const float*)0, 256, 64);
    scan_kernel<<<2, 256>>>();                                                       // 4
    copycur_kernel<<<(N_ + 255) / 256, 256>>>();                                     // 5
    fill_kernel<<<(E_ + 255) / 256, 256>>>(row, col);                                // 6
    mma_gemm<<<dim3(4, (N_ + 127) / 128), 256, SMEM_MMA>>>(                          // 7
        x, 512, N_, pBx_hi, pBx_lo, p_xl1, p_xr1, b1l, b1r, 256, 256);

    // self-loop attrs (gather by col, float4 lanes)
    lep_kernel<<<N_, 96>>>();

    // layer 1 attention (warp per node-head-pair)
    att1_kernel<<<(N_ * 2 * 32 + 255) / 256, 256>>>(att1, bias1);

    // layer 2 transforms
    mma_gemm<<<dim3(1, (N_ + 127) / 128), 256, SMEM_MMA>>>(
        p_h1, 256, N_, pBh_hi, pBh_lo, p_xl2, p_xr2, b2l, b2r, 64, 64);

    // layer 2 attention + fused max pool
    att2_kernel<<<(N_ * 32 + 255) / 256, 256>>>(att2, bias2, batch);

    final_kernel<<<G_, 256>>>(ln_g, ln_b, clfW, clfb, out, out_size);
}